// round 13
// baseline (speedup 1.0000x reference)
#include <cuda_runtime.h>
#include <cuda_bf16.h>

#define BB 4096
#define TT 365
#define HORIZON 7
#define NCTA 128
#define NTH 512

// ---- SMEM byte offsets (all arrays 128B-row pitch, SW128 swizzled) ----
#define OFF_W0H   0u          // Whh0 hi   [256 cols][64 k] bf16
#define OFF_W0L   32768u      // Whh0 lo
#define OFF_W1AH  65536u      // Wih1 hi   (L1, k from h0)
#define OFF_W1AL  98304u
#define OFF_W1BH  131072u     // Whh1 hi   (L1, k from h1)
#define OFF_W1BL  163840u
#define OFF_AH0   196608u     // h0[buf 2][split 2]: 32x64 bf16 = 4096B each
#define OFF_AH1   212992u     // h1[buf 2][split 2]
#define SMEM_BYTES 229376u

// decoder FC scratch (per-CTA slices of device globals; no allocation)
__device__ float g_pp[NCTA][8][32];
__device__ float g_fb[NCTA][32];

// Named barriers: 1/2 = h0 published (parity), 3/4 = h0 slot free (parity),
// 5 = L0-internal, 6 = L1-internal. Parity split bounds producer lead.
#define BAR_SYNC(id, n)   asm volatile("bar.sync %0, %1;" :: "r"(id), "r"(n) : "memory")
#define BAR_ARRIVE(id, n) asm volatile("bar.arrive %0, %1;" :: "r"(id), "r"(n) : "memory")

__device__ __forceinline__ unsigned swz(unsigned o) { return o ^ ((o >> 3) & 0x70u); }

__device__ __forceinline__ void ldsm4(unsigned &r0, unsigned &r1, unsigned &r2, unsigned &r3,
                                      unsigned a) {
    asm volatile("ldmatrix.sync.aligned.m8n8.x4.shared.b16 {%0,%1,%2,%3}, [%4];"
                 : "=r"(r0), "=r"(r1), "=r"(r2), "=r"(r3) : "r"(a));
}

__device__ __forceinline__ void mma16816(float d[4], unsigned a0, unsigned a1, unsigned a2,
                                         unsigned a3, unsigned b0, unsigned b1) {
    asm volatile("mma.sync.aligned.m16n8k16.row.col.f32.bf16.bf16.f32 "
                 "{%0,%1,%2,%3},{%4,%5,%6,%7},{%8,%9},{%0,%1,%2,%3};"
                 : "+f"(d[0]), "+f"(d[1]), "+f"(d[2]), "+f"(d[3])
                 : "r"(a0), "r"(a1), "r"(a2), "r"(a3), "r"(b0), "r"(b1));
}

__device__ __forceinline__ float sigm(float v) {
    return __fdividef(1.f, 1.f + __expf(-v));
}
__device__ __forceinline__ float tanh_(float v) {
    float a = fabsf(v);
    float e = __expf(-2.f * a);
    float r = __fdividef(1.f - e, 1.f + e);
    return copysignf(r, v);
}

// One m16 x n32 pass: acc[4][4] += A(16x64 split) @ W(64x32-block split).
// Fragment live set: 8 A-regs + 8 B-regs (sequential per ks) -> no spill.
__device__ __forceinline__ void gemm16(float acc[4][4], unsigned sb,
                                       unsigned aH, unsigned aL,
                                       unsigned wH, unsigned wL,
                                       unsigned raOff, unsigned cbOff) {
    #pragma unroll
    for (int ks = 0; ks < 4; ++ks) {
        unsigned ah0, ah1, ah2, ah3, al0, al1, al2, al3;
        ldsm4(ah0, ah1, ah2, ah3, sb + aH + swz(raOff + ks * 32));
        ldsm4(al0, al1, al2, al3, sb + aL + swz(raOff + ks * 32));
        #pragma unroll
        for (int tp = 0; tp < 2; ++tp) {
            unsigned bh0, bh1, bh2, bh3, bl0, bl1, bl2, bl3;
            ldsm4(bh0, bh1, bh2, bh3, sb + wH + swz(cbOff + tp * 2048 + ks * 32));
            ldsm4(bl0, bl1, bl2, bl3, sb + wL + swz(cbOff + tp * 2048 + ks * 32));
            mma16816(acc[2 * tp],     ah0, ah1, ah2, ah3, bh0, bh1);
            mma16816(acc[2 * tp],     ah0, ah1, ah2, ah3, bl0, bl1);
            mma16816(acc[2 * tp],     al0, al1, al2, al3, bh0, bh1);
            mma16816(acc[2 * tp + 1], ah0, ah1, ah2, ah3, bh2, bh3);
            mma16816(acc[2 * tp + 1], ah0, ah1, ah2, ah3, bl2, bl3);
            mma16816(acc[2 * tp + 1], al0, al1, al2, al3, bh2, bh3);
        }
    }
}

// Split LSTM cell: even lane owns nt 0,1; odd lane owns nt 2,3. 8 shfl.
__device__ __forceinline__ void cellq2(const float acc[4][4], float cst[4],
                                       float hvo[2][2], int ifh) {
    float recv[2][4];
    #pragma unroll
    for (int tt = 0; tt < 2; ++tt)
        #pragma unroll
        for (int e = 0; e < 4; ++e) {
            float send = ifh ? acc[2 + tt][e] : acc[tt][e];
            recv[tt][e] = __shfl_xor_sync(0xFFFFFFFFu, send, 1);
        }
    #pragma unroll
    for (int tt = 0; tt < 2; ++tt) {
        int t = ifh ? tt : 2 + tt;
        float gi = ifh ? acc[t][0] : recv[tt][0];
        float gf = ifh ? acc[t][1] : recv[tt][1];
        float gg = ifh ? recv[tt][0] : acc[t][0];
        float go = ifh ? recv[tt][1] : acc[t][1];
        float cn = sigm(gf) * cst[2 * tt] + sigm(gi) * tanh_(gg);
        cst[2 * tt] = cn;
        hvo[tt][0] = sigm(go) * tanh_(cn);
        gi = ifh ? acc[t][2] : recv[tt][2];
        gf = ifh ? acc[t][3] : recv[tt][3];
        gg = ifh ? recv[tt][2] : acc[t][2];
        go = ifh ? recv[tt][3] : acc[t][3];
        cn = sigm(gf) * cst[2 * tt + 1] + sigm(gi) * tanh_(gg);
        cst[2 * tt + 1] = cn;
        hvo[tt][1] = sigm(go) * tanh_(cn);
    }
}

__device__ __forceinline__ void storehq(char *smp, unsigned offH, unsigned offL,
                                        const float hvo[2][2], int nb, int ug,
                                        int rA, int rB, int ifh) {
    #pragma unroll
    for (int tt = 0; tt < 2; ++tt) {
        int t = ifh ? tt : 2 + tt;
        int u = 2 * (nb + t) + ug;
        unsigned oA = swz((unsigned)(rA * 128 + u * 2));
        unsigned oB = swz((unsigned)(rB * 128 + u * 2));
        __nv_bfloat16 hA = __float2bfloat16(hvo[tt][0]);
        __nv_bfloat16 lA = __float2bfloat16(hvo[tt][0] - __bfloat162float(hA));
        __nv_bfloat16 hB = __float2bfloat16(hvo[tt][1]);
        __nv_bfloat16 lB = __float2bfloat16(hvo[tt][1] - __bfloat162float(hB));
        *(__nv_bfloat16 *)(smp + offH + oA) = hA;
        *(__nv_bfloat16 *)(smp + offL + oA) = lA;
        *(__nv_bfloat16 *)(smp + offH + oB) = hB;
        *(__nv_bfloat16 *)(smp + offL + oB) = lB;
    }
}

__device__ void store_w(char *smp, unsigned offH, unsigned offL, const float *__restrict__ raw) {
    for (int e = threadIdx.x; e < 256 * 64; e += NTH) {
        int R = e >> 6, k = e & 63;
        int c = (R & 63) * 4 + (R >> 6);
        float w = raw[e];
        __nv_bfloat16 hi = __float2bfloat16(w);
        __nv_bfloat16 lo = __float2bfloat16(w - __bfloat162float(hi));
        unsigned o = swz((unsigned)(c * 128 + k * 2));
        *(__nv_bfloat16 *)(smp + offH + o) = hi;
        *(__nv_bfloat16 *)(smp + offL + o) = lo;
    }
}

__global__ void __launch_bounds__(NTH, 1)
lstm_kernel(const float *__restrict__ x,
            const float *__restrict__ eWih0, const float *__restrict__ eWhh0,
            const float *__restrict__ eb0,
            const float *__restrict__ eWih1, const float *__restrict__ eWhh1,
            const float *__restrict__ eb1,
            const float *__restrict__ dWih0, const float *__restrict__ dWhh0,
            const float *__restrict__ db0,
            const float *__restrict__ dWih1, const float *__restrict__ dWhh1,
            const float *__restrict__ db1,
            const float *__restrict__ fcW, const float *__restrict__ fcb,
            float *__restrict__ out) {
    extern __shared__ char smem[];
    unsigned sb = (unsigned)__cvta_generic_to_shared(smem);

    const int tid = threadIdx.x;
    const int lane = tid & 31;
    const int wid = tid >> 5;
    const int jw = wid & 7;            // n-block: units 8jw..8jw+7
    const int nb = 4 * jw;
    const int grp0 = (wid < 8);        // L0 group
    const int blk = blockIdx.x;

    const int ifh = !(lane & 1);
    const int ug = (lane >> 1) & 1;
    const int rA = lane >> 2;
    const int rB = rA + 8;

    const unsigned ra0 = (unsigned)(((lane & 7) + (lane & 8)) * 128 + ((lane >> 4) & 1) * 16);
    const unsigned ra1 = ra0 + 16 * 128;
    const unsigned cbOff = (unsigned)((8 * nb + (lane & 7) + 8 * ((lane >> 4) & 1)) * 128
                                      + ((lane >> 3) & 1) * 16);

    int cI[4][2];
    #pragma unroll
    for (int t = 0; t < 4; ++t) {
        int c0 = 8 * (nb + t) + ((lane & 3) << 1);
        cI[t][0] = (c0 & 3) * 64 + (c0 >> 2);
        cI[t][1] = ((c0 + 1) & 3) * 64 + ((c0 + 1) >> 2);
    }

    // ---------- encoder weights ----------
    store_w(smem, OFF_W0H, OFF_W0L, eWhh0);
    store_w(smem, OFF_W1AH, OFF_W1AL, eWih1);
    store_w(smem, OFF_W1BH, OFF_W1BL, eWhh1);
    for (int i = tid; i < 8192; i += NTH) ((float *)(smem + OFF_AH0))[i] = 0.f;

    float bA[4][2], bB[4][2];          // grp0: b0, Wih0.  grp1: b1, 0
    #pragma unroll
    for (int t = 0; t < 4; ++t) {
        if (grp0) {
            bA[t][0] = eb0[cI[t][0]]; bA[t][1] = eb0[cI[t][1]];
            bB[t][0] = eWih0[cI[t][0]]; bB[t][1] = eWih0[cI[t][1]];
        } else {
            bA[t][0] = eb1[cI[t][0]]; bA[t][1] = eb1[cI[t][1]];
            bB[t][0] = 0.f; bB[t][1] = 0.f;
        }
    }
    __syncthreads();

    float cst[2][4];
    #pragma unroll
    for (int m = 0; m < 2; ++m)
        #pragma unroll
        for (int i = 0; i < 4; ++i) cst[m][i] = 0.f;

    // ================= encoder: warp-specialized pipeline =================
    if (grp0) {
        const float *xbase = x + blk * 32 * TT;
        float xv[4];
        xv[0] = xbase[rA * TT]; xv[1] = xbase[rB * TT];
        xv[2] = xbase[(rA + 16) * TT]; xv[3] = xbase[(rB + 16) * TT];
        for (int t = 0; t < TT; ++t) {
            float xn[4] = {0.f, 0.f, 0.f, 0.f};
            if (t + 1 < TT) {
                xn[0] = xbase[rA * TT + t + 1]; xn[1] = xbase[rB * TT + t + 1];
                xn[2] = xbase[(rA + 16) * TT + t + 1]; xn[3] = xbase[(rB + 16) * TT + t + 1];
            }
            unsigned h0r = OFF_AH0 + (unsigned)(t & 1) * 8192u;
            unsigned h0w = OFF_AH0 + (unsigned)((t + 1) & 1) * 8192u;

            // m-tile 0
            float acc0[4][4];
            #pragma unroll
            for (int tt = 0; tt < 4; ++tt) {
                acc0[tt][0] = fmaf(xv[0], bB[tt][0], bA[tt][0]);
                acc0[tt][1] = fmaf(xv[0], bB[tt][1], bA[tt][1]);
                acc0[tt][2] = fmaf(xv[1], bB[tt][0], bA[tt][0]);
                acc0[tt][3] = fmaf(xv[1], bB[tt][1], bA[tt][1]);
            }
            gemm16(acc0, sb, h0r, h0r + 4096, OFF_W0H, OFF_W0L, ra0, cbOff);
            float hv0[2][2];
            cellq2(acc0, cst[0], hv0, ifh);
            // m-tile 1 (sequential pass: reuses the fragment registers)
            float acc1[4][4];
            #pragma unroll
            for (int tt = 0; tt < 4; ++tt) {
                acc1[tt][0] = fmaf(xv[2], bB[tt][0], bA[tt][0]);
                acc1[tt][1] = fmaf(xv[2], bB[tt][1], bA[tt][1]);
                acc1[tt][2] = fmaf(xv[3], bB[tt][0], bA[tt][0]);
                acc1[tt][3] = fmaf(xv[3], bB[tt][1], bA[tt][1]);
            }
            gemm16(acc1, sb, h0r, h0r + 4096, OFF_W0H, OFF_W0L, ra1, cbOff);
            float hv1[2][2];
            cellq2(acc1, cst[1], hv1, ifh);

            BAR_SYNC(3 + (t & 1), 512);                 // slot free (L1 done with h0(t-2))
            storehq(smem, h0w, h0w + 4096, hv0, nb, ug, rA, rB, ifh);
            storehq(smem, h0w, h0w + 4096, hv1, nb, ug, rA + 16, rB + 16, ifh);
            BAR_SYNC(5, 256);                           // L0-internal visibility
            BAR_ARRIVE(1 + (t & 1), 512);               // publish h0(t)
            xv[0] = xn[0]; xv[1] = xn[1]; xv[2] = xn[2]; xv[3] = xn[3];
        }
    } else {
        BAR_ARRIVE(3, 512);
        BAR_ARRIVE(4, 512);
        for (int s = 0; s < TT; ++s) {
            unsigned h1r = OFF_AH1 + (unsigned)(s & 1) * 8192u;
            unsigned h1w = OFF_AH1 + (unsigned)((s + 1) & 1) * 8192u;
            unsigned h0c = OFF_AH0 + (unsigned)((s + 1) & 1) * 8192u;   // h0(s)

            float acc0[4][4], acc1[4][4];
            #pragma unroll
            for (int tt = 0; tt < 4; ++tt) {
                acc0[tt][0] = bA[tt][0]; acc0[tt][1] = bA[tt][1];
                acc0[tt][2] = bA[tt][0]; acc0[tt][3] = bA[tt][1];
                acc1[tt][0] = bA[tt][0]; acc1[tt][1] = bA[tt][1];
                acc1[tt][2] = bA[tt][0]; acc1[tt][3] = bA[tt][1];
            }
            // hoisted: h1(s-1) @ Whh1 while L0 computes h0(s)
            gemm16(acc0, sb, h1r, h1r + 4096, OFF_W1BH, OFF_W1BL, ra0, cbOff);
            gemm16(acc1, sb, h1r, h1r + 4096, OFF_W1BH, OFF_W1BL, ra1, cbOff);
            BAR_SYNC(1 + (s & 1), 512);                 // wait h0(s)
            gemm16(acc0, sb, h0c, h0c + 4096, OFF_W1AH, OFF_W1AL, ra0, cbOff);
            float hv0[2][2];
            cellq2(acc0, cst[0], hv0, ifh);
            gemm16(acc1, sb, h0c, h0c + 4096, OFF_W1AH, OFF_W1AL, ra1, cbOff);
            BAR_ARRIVE(3 + (s & 1), 512);               // done reading h0(s)
            float hv1[2][2];
            cellq2(acc1, cst[1], hv1, ifh);
            storehq(smem, h1w, h1w + 4096, hv0, nb, ug, rA, rB, ifh);
            storehq(smem, h1w, h1w + 4096, hv1, nb, ug, rA + 16, rB + 16, ifh);
            BAR_SYNC(6, 256);                           // L1-internal visibility
        }
    }
    __syncthreads();

    // ---------- decoder weights ----------
    store_w(smem, OFF_W0H, OFF_W0L, dWhh0);
    store_w(smem, OFF_W1AH, OFF_W1AL, dWih1);
    store_w(smem, OFF_W1BH, OFF_W1BL, dWhh1);
    float fcw2[2] = {0.f, 0.f};
    #pragma unroll
    for (int t = 0; t < 4; ++t) {
        if (grp0) {
            bA[t][0] = db0[cI[t][0]]; bA[t][1] = db0[cI[t][1]];
            bB[t][0] = dWih0[cI[t][0]]; bB[t][1] = dWih0[cI[t][1]];
        } else {
            bA[t][0] = db1[cI[t][0]]; bA[t][1] = db1[cI[t][1]];
        }
    }
    if (!grp0) {
        #pragma unroll
        for (int tt = 0; tt < 2; ++tt) {
            int t = ifh ? tt : 2 + tt;
            fcw2[tt] = fcW[2 * (nb + t) + ug];
        }
    }
    const float fcbv = fcb[0];
    __syncthreads();

    // ---------- decoder: 7 steps, common path, group-gated ----------
    float din[4] = {0.f, 0.f, 0.f, 0.f};
    for (int s = 0; s < HORIZON; ++s) {
        unsigned rp = (unsigned)((TT + s) & 1);
        unsigned h0r = OFF_AH0 + rp * 8192u, h0w = OFF_AH0 + (rp ^ 1) * 8192u;
        unsigned h1r = OFF_AH1 + rp * 8192u, h1w = OFF_AH1 + (rp ^ 1) * 8192u;

        if (grp0) {
            float acc0[4][4], acc1[4][4];
            #pragma unroll
            for (int tt = 0; tt < 4; ++tt) {
                acc0[tt][0] = fmaf(din[0], bB[tt][0], bA[tt][0]);
                acc0[tt][1] = fmaf(din[0], bB[tt][1], bA[tt][1]);
                acc0[tt][2] = fmaf(din[1], bB[tt][0], bA[tt][0]);
                acc0[tt][3] = fmaf(din[1], bB[tt][1], bA[tt][1]);
                acc1[tt][0] = fmaf(din[2], bB[tt][0], bA[tt][0]);
                acc1[tt][1] = fmaf(din[2], bB[tt][1], bA[tt][1]);
                acc1[tt][2] = fmaf(din[3], bB[tt][0], bA[tt][0]);
                acc1[tt][3] = fmaf(din[3], bB[tt][1], bA[tt][1]);
            }
            gemm16(acc0, sb, h0r, h0r + 4096, OFF_W0H, OFF_W0L, ra0, cbOff);
            gemm16(acc1, sb, h0r, h0r + 4096, OFF_W0H, OFF_W0L, ra1, cbOff);
            float hv0[2][2], hv1[2][2];
            cellq2(acc0, cst[0], hv0, ifh);
            cellq2(acc1, cst[1], hv1, ifh);
            storehq(smem, h0w, h0w + 4096, hv0, nb, ug, rA, rB, ifh);
            storehq(smem, h0w, h0w + 4096, hv1, nb, ug, rA + 16, rB + 16, ifh);
        }
        __syncthreads();
        if (!grp0) {
            float acc0[4][4], acc1[4][4];
            #pragma unroll
            for (int tt = 0; tt < 4; ++tt) {
                acc0[tt][0] = bA[tt][0]; acc0[tt][1] = bA[tt][1];
                acc0[tt][2] = bA[tt][0]; acc0[tt][3] = bA[tt][1];
                acc1[tt][0] = bA[tt][0]; acc1[tt][1] = bA[tt][1];
                acc1[tt][2] = bA[tt][0]; acc1[tt][3] = bA[tt][1];
            }
            gemm16(acc0, sb, h1r, h1r + 4096, OFF_W1BH, OFF_W1BL, ra0, cbOff);
            gemm16(acc0, sb, h0w, h0w + 4096, OFF_W1AH, OFF_W1AL, ra0, cbOff);
            gemm16(acc1, sb, h1r, h1r + 4096, OFF_W1BH, OFF_W1BL, ra1, cbOff);
            gemm16(acc1, sb, h0w, h0w + 4096, OFF_W1AH, OFF_W1AL, ra1, cbOff);
            float hv0[2][2], hv1[2][2];
            cellq2(acc0, cst[0], hv0, ifh);
            cellq2(acc1, cst[1], hv1, ifh);
            storehq(smem, h1w, h1w + 4096, hv0, nb, ug, rA, rB, ifh);
            storehq(smem, h1w, h1w + 4096, hv1, nb, ug, rA + 16, rB + 16, ifh);
            float v00 = hv0[0][0] * fcw2[0] + hv0[1][0] * fcw2[1];
            float v01 = hv0[0][1] * fcw2[0] + hv0[1][1] * fcw2[1];
            float v10 = hv1[0][0] * fcw2[0] + hv1[1][0] * fcw2[1];
            float v11 = hv1[0][1] * fcw2[0] + hv1[1][1] * fcw2[1];
            v00 += __shfl_xor_sync(0xFFFFFFFFu, v00, 1);
            v01 += __shfl_xor_sync(0xFFFFFFFFu, v01, 1);
            v10 += __shfl_xor_sync(0xFFFFFFFFu, v10, 1);
            v11 += __shfl_xor_sync(0xFFFFFFFFu, v11, 1);
            v00 += __shfl_xor_sync(0xFFFFFFFFu, v00, 2);
            v01 += __shfl_xor_sync(0xFFFFFFFFu, v01, 2);
            v10 += __shfl_xor_sync(0xFFFFFFFFu, v10, 2);
            v11 += __shfl_xor_sync(0xFFFFFFFFu, v11, 2);
            if ((lane & 3) == 0) {
                g_pp[blk][jw][rA] = v00;
                g_pp[blk][jw][rB] = v01;
                g_pp[blk][jw][rA + 16] = v10;
                g_pp[blk][jw][rB + 16] = v11;
            }
        }
        __syncthreads();
        if (tid < 32) {
            float sum = fcbv;
            #pragma unroll
            for (int j = 0; j < 8; ++j) sum += g_pp[blk][j][tid];
            out[(blk * 32 + tid) * HORIZON + s] = sum;
            g_fb[blk][tid] = sum;
        }
        __syncthreads();
        if (grp0) {
            din[0] = g_fb[blk][rA];
            din[1] = g_fb[blk][rB];
            din[2] = g_fb[blk][rA + 16];
            din[3] = g_fb[blk][rB + 16];
        }
    }
}

extern "C" void kernel_launch(void *const *d_in, const int *in_sizes, int n_in,
                              void *d_out, int out_size) {
    cudaFuncSetAttribute(lstm_kernel, cudaFuncAttributeMaxDynamicSharedMemorySize, SMEM_BYTES);
    lstm_kernel<<<NCTA, NTH, SMEM_BYTES>>>(
        (const float *)d_in[0],
        (const float *)d_in[1], (const float *)d_in[2], (const float *)d_in[3],
        (const float *)d_in[4], (const float *)d_in[5], (const float *)d_in[6],
        (const float *)d_in[7], (const float *)d_in[8], (const float *)d_in[9],
        (const float *)d_in[10], (const float *)d_in[11], (const float *)d_in[12],
        (const float *)d_in[13], (const float *)d_in[14],
        (float *)d_out);
}

// round 14
// speedup vs baseline: 1.1987x; 1.1987x over previous
#include <cuda_runtime.h>
#include <cuda_bf16.h>

#define BB 4096
#define TT 365
#define HORIZON 7
#define NCTA 128
#define NTH 512

// ---- SMEM byte offsets (all arrays 128B-row pitch, SW128 swizzled) ----
#define OFF_W0H   0u          // Whh0 hi   [256 cols][64 k] bf16
#define OFF_W0L   32768u      // Whh0 lo
#define OFF_W1AH  65536u      // Wih1 hi   (L1, k from h0)
#define OFF_W1AL  98304u
#define OFF_W1BH  131072u     // Whh1 hi   (L1, k from h1)
#define OFF_W1BL  163840u
#define OFF_AH0   196608u     // h0[buf 2][split 2]: 32x64 bf16 = 4096B each
#define OFF_AH1   212992u     // h1[buf 2][split 2]
#define SMEM_BYTES 229376u

// decoder FC scratch (per-CTA slices of device globals; no allocation)
__device__ float g_pp[NCTA][16][32];
__device__ float g_fb[NCTA][32];

__device__ __forceinline__ unsigned swz(unsigned o) { return o ^ ((o >> 3) & 0x70u); }

__device__ __forceinline__ void ldsm4(unsigned &r0, unsigned &r1, unsigned &r2, unsigned &r3,
                                      unsigned a) {
    asm volatile("ldmatrix.sync.aligned.m8n8.x4.shared.b16 {%0,%1,%2,%3}, [%4];"
                 : "=r"(r0), "=r"(r1), "=r"(r2), "=r"(r3) : "r"(a));
}

__device__ __forceinline__ void mma16816(float d[4], unsigned a0, unsigned a1, unsigned a2,
                                         unsigned a3, unsigned b0, unsigned b1) {
    asm volatile("mma.sync.aligned.m16n8k16.row.col.f32.bf16.bf16.f32 "
                 "{%0,%1,%2,%3},{%4,%5,%6,%7},{%8,%9},{%0,%1,%2,%3};"
                 : "+f"(d[0]), "+f"(d[1]), "+f"(d[2]), "+f"(d[3])
                 : "r"(a0), "r"(a1), "r"(a2), "r"(a3), "r"(b0), "r"(b1));
}

__device__ __forceinline__ float sigm(float v) {
    return __fdividef(1.f, 1.f + __expf(-v));
}
__device__ __forceinline__ float tanh_(float v) {
    float a = fabsf(v);
    float e = __expf(-2.f * a);
    float r = __fdividef(1.f - e, 1.f + e);
    return copysignf(r, v);
}

// Dual-stream GEMM: accA += A[rows raA] @ W, accB += A[rows raB] @ W.
// W fragments loaded ONCE per ks, shared by both streams. m16n16 per stream.
// 3-product bf16 split. Two independent MMA chains -> ILP fills latency.
__device__ __forceinline__ void gemm_dual(float accA[2][4], float accB[2][4], unsigned sb,
                                          unsigned aH, unsigned aL,
                                          unsigned wH, unsigned wL,
                                          unsigned raA, unsigned raB, unsigned cbOff) {
    #pragma unroll
    for (int ks = 0; ks < 4; ++ks) {
        unsigned bh0, bh1, bh2, bh3, bl0, bl1, bl2, bl3;
        ldsm4(bh0, bh1, bh2, bh3, sb + wH + swz(cbOff + ks * 32));
        ldsm4(bl0, bl1, bl2, bl3, sb + wL + swz(cbOff + ks * 32));
        unsigned a0, a1, a2, a3, l0, l1, l2, l3;
        ldsm4(a0, a1, a2, a3, sb + aH + swz(raA + ks * 32));
        ldsm4(l0, l1, l2, l3, sb + aL + swz(raA + ks * 32));
        mma16816(accA[0], a0, a1, a2, a3, bh0, bh1);
        mma16816(accA[0], a0, a1, a2, a3, bl0, bl1);
        mma16816(accA[0], l0, l1, l2, l3, bh0, bh1);
        mma16816(accA[1], a0, a1, a2, a3, bh2, bh3);
        mma16816(accA[1], a0, a1, a2, a3, bl2, bl3);
        mma16816(accA[1], l0, l1, l2, l3, bh2, bh3);
        unsigned c0, c1, c2, c3, m0, m1, m2, m3;
        ldsm4(c0, c1, c2, c3, sb + aH + swz(raB + ks * 32));
        ldsm4(m0, m1, m2, m3, sb + aL + swz(raB + ks * 32));
        mma16816(accB[0], c0, c1, c2, c3, bh0, bh1);
        mma16816(accB[0], c0, c1, c2, c3, bl0, bl1);
        mma16816(accB[0], m0, m1, m2, m3, bh0, bh1);
        mma16816(accB[1], c0, c1, c2, c3, bh2, bh3);
        mma16816(accB[1], c0, c1, c2, c3, bl2, bl3);
        mma16816(accB[1], m0, m1, m2, m3, bh2, bh3);
    }
}

// Per-stream split cell: even lane owns tile 0 (its unit), odd owns tile 1.
// 4 shfl. hvo[row 0/1] = h of owned unit at rows rA, rB. cst[2] likewise.
__device__ __forceinline__ void cell_s(const float acc[2][4], float cst[2],
                                       float hvo[2], int ifh) {
    float recv[4];
    #pragma unroll
    for (int e = 0; e < 4; ++e) {
        float send = ifh ? acc[1][e] : acc[0][e];
        recv[e] = __shfl_xor_sync(0xFFFFFFFFu, send, 1);
    }
    const float *own = ifh ? acc[0] : acc[1];
    float gi = ifh ? own[0] : recv[0];
    float gf = ifh ? own[1] : recv[1];
    float gg = ifh ? recv[0] : own[0];
    float go = ifh ? recv[1] : own[1];
    float cn = sigm(gf) * cst[0] + sigm(gi) * tanh_(gg);
    cst[0] = cn;
    hvo[0] = sigm(go) * tanh_(cn);
    gi = ifh ? own[2] : recv[2];
    gf = ifh ? own[3] : recv[3];
    gg = ifh ? recv[2] : own[2];
    go = ifh ? recv[3] : own[3];
    cn = sigm(gf) * cst[1] + sigm(gi) * tanh_(gg);
    cst[1] = cn;
    hvo[1] = sigm(go) * tanh_(cn);
}

// Store owned unit's h (bf16 hi/lo) for rows rA, rB.
__device__ __forceinline__ void store_s(char *smp, unsigned offH, unsigned offL,
                                        const float hvo[2], int uo, int rA, int rB) {
    unsigned oA = swz((unsigned)(rA * 128 + uo * 2));
    unsigned oB = swz((unsigned)(rB * 128 + uo * 2));
    __nv_bfloat16 hA = __float2bfloat16(hvo[0]);
    __nv_bfloat16 lA = __float2bfloat16(hvo[0] - __bfloat162float(hA));
    __nv_bfloat16 hB = __float2bfloat16(hvo[1]);
    __nv_bfloat16 lB = __float2bfloat16(hvo[1] - __bfloat162float(hB));
    *(__nv_bfloat16 *)(smp + offH + oA) = hA;
    *(__nv_bfloat16 *)(smp + offL + oA) = lA;
    *(__nv_bfloat16 *)(smp + offH + oB) = hB;
    *(__nv_bfloat16 *)(smp + offL + oB) = lB;
}

// Split-store raw fp32 weights [256 gate-rows][64 k] into gate-interleaved
// swizzled bf16 hi/lo: col c = u*4 + g, addr = swz(c*128 + k*2).
__device__ void store_w(char *smp, unsigned offH, unsigned offL, const float *__restrict__ raw) {
    for (int e = threadIdx.x; e < 256 * 64; e += NTH) {
        int R = e >> 6, k = e & 63;
        int c = (R & 63) * 4 + (R >> 6);
        float w = raw[e];
        __nv_bfloat16 hi = __float2bfloat16(w);
        __nv_bfloat16 lo = __float2bfloat16(w - __bfloat162float(hi));
        unsigned o = swz((unsigned)(c * 128 + k * 2));
        *(__nv_bfloat16 *)(smp + offH + o) = hi;
        *(__nv_bfloat16 *)(smp + offL + o) = lo;
    }
}

__global__ void __launch_bounds__(NTH, 1)
lstm_kernel(const float *__restrict__ x,
            const float *__restrict__ eWih0, const float *__restrict__ eWhh0,
            const float *__restrict__ eb0,
            const float *__restrict__ eWih1, const float *__restrict__ eWhh1,
            const float *__restrict__ eb1,
            const float *__restrict__ dWih0, const float *__restrict__ dWhh0,
            const float *__restrict__ db0,
            const float *__restrict__ dWih1, const float *__restrict__ dWhh1,
            const float *__restrict__ db1,
            const float *__restrict__ fcW, const float *__restrict__ fcb,
            float *__restrict__ out) {
    extern __shared__ char smem[];
    unsigned sb = (unsigned)__cvta_generic_to_shared(smem);

    const int tid = threadIdx.x;
    const int lane = tid & 31;
    const int jw = tid >> 5;           // warp = n16 block: units 4jw..4jw+3
    const int blk = blockIdx.x;

    const int ifh = !(lane & 1);       // even lane holds (i,f); odd (g,o)
    const int rA = lane >> 2;          // stream-local rows rA, rA+8
    const int rB = rA + 8;
    // owned unit: even lane -> tile0 units, odd -> tile1 units
    const int uo = 4 * jw + (ifh ? ((lane >> 1) & 1) : 2 + ((lane >> 1) & 1));

    // ldmatrix address bases
    const unsigned raA = (unsigned)(((lane & 7) + (lane & 8)) * 128 + ((lane >> 4) & 1) * 16);
    const unsigned raB = raA + 16 * 128;
    const unsigned cbOff = (unsigned)((16 * jw + (lane & 7) + 8 * ((lane >> 4) & 1)) * 128
                                      + ((lane >> 3) & 1) * 16);

    // lane's gate columns: tile nt, pair p -> col 16jw + 8nt + 2(lane&3) + p
    int cI[2][2];
    #pragma unroll
    for (int nt = 0; nt < 2; ++nt) {
        int c0 = 16 * jw + 8 * nt + ((lane & 3) << 1);
        cI[nt][0] = (c0 & 3) * 64 + (c0 >> 2);
        cI[nt][1] = ((c0 + 1) & 3) * 64 + ((c0 + 1) >> 2);
    }

    // ---------- encoder weights ----------
    store_w(smem, OFF_W0H, OFF_W0L, eWhh0);
    store_w(smem, OFF_W1AH, OFF_W1AL, eWih1);
    store_w(smem, OFF_W1BH, OFF_W1BL, eWhh1);
    for (int i = tid; i < 8192; i += NTH) ((float *)(smem + OFF_AH0))[i] = 0.f;

    float b0c[2][2], b1c[2][2], wic[2][2];
    #pragma unroll
    for (int nt = 0; nt < 2; ++nt) {
        b0c[nt][0] = eb0[cI[nt][0]]; b0c[nt][1] = eb0[cI[nt][1]];
        b1c[nt][0] = eb1[cI[nt][0]]; b1c[nt][1] = eb1[cI[nt][1]];
        wic[nt][0] = eWih0[cI[nt][0]]; wic[nt][1] = eWih0[cI[nt][1]];
    }
    __syncthreads();

    float c0A[2] = {0.f, 0.f}, c0B[2] = {0.f, 0.f};
    float c1A[2] = {0.f, 0.f}, c1B[2] = {0.f, 0.f};

    const float *xbase = x + blk * 32 * TT;
    float xv[4];
    xv[0] = xbase[rA * TT];            // stream A rows rA, rB
    xv[1] = xbase[rB * TT];
    xv[2] = xbase[(rA + 16) * TT];     // stream B rows rA+16, rB+16
    xv[3] = xbase[(rB + 16) * TT];

    // ---------- encoder: 365 steps, 1 barrier/step, dual-stream ILP ----------
    for (int t = 0; t < TT; ++t) {
        float xn[4] = {0.f, 0.f, 0.f, 0.f};
        if (t + 1 < TT) {
            xn[0] = xbase[rA * TT + t + 1];
            xn[1] = xbase[rB * TT + t + 1];
            xn[2] = xbase[(rA + 16) * TT + t + 1];
            xn[3] = xbase[(rB + 16) * TT + t + 1];
        }
        unsigned h0r = OFF_AH0 + (unsigned)(t & 1) * 8192u;
        unsigned h0w = OFF_AH0 + (unsigned)((t + 1) & 1) * 8192u;
        unsigned h1r = OFF_AH1 + (unsigned)(t & 1) * 8192u;
        unsigned h1w = OFF_AH1 + (unsigned)((t + 1) & 1) * 8192u;

        // phase 1: layer 0 for both streams
        float aA[2][4], aB[2][4];
        #pragma unroll
        for (int nt = 0; nt < 2; ++nt) {
            aA[nt][0] = fmaf(xv[0], wic[nt][0], b0c[nt][0]);
            aA[nt][1] = fmaf(xv[0], wic[nt][1], b0c[nt][1]);
            aA[nt][2] = fmaf(xv[1], wic[nt][0], b0c[nt][0]);
            aA[nt][3] = fmaf(xv[1], wic[nt][1], b0c[nt][1]);
            aB[nt][0] = fmaf(xv[2], wic[nt][0], b0c[nt][0]);
            aB[nt][1] = fmaf(xv[2], wic[nt][1], b0c[nt][1]);
            aB[nt][2] = fmaf(xv[3], wic[nt][0], b0c[nt][0]);
            aB[nt][3] = fmaf(xv[3], wic[nt][1], b0c[nt][1]);
        }
        gemm_dual(aA, aB, sb, h0r, h0r + 4096, OFF_W0H, OFF_W0L, raA, raB, cbOff);
        float hA[2], hB[2];
        cell_s(aA, c0A, hA, ifh);
        cell_s(aB, c0B, hB, ifh);
        store_s(smem, h0w, h0w + 4096, hA, uo, rA, rB);
        store_s(smem, h0w, h0w + 4096, hB, uo, rA + 16, rB + 16);
        __syncthreads();

        // phase 2: layer 1 for both streams (K=128: h0_cur + h1_prev)
        #pragma unroll
        for (int nt = 0; nt < 2; ++nt) {
            aA[nt][0] = b1c[nt][0]; aA[nt][1] = b1c[nt][1];
            aA[nt][2] = b1c[nt][0]; aA[nt][3] = b1c[nt][1];
            aB[nt][0] = b1c[nt][0]; aB[nt][1] = b1c[nt][1];
            aB[nt][2] = b1c[nt][0]; aB[nt][3] = b1c[nt][1];
        }
        gemm_dual(aA, aB, sb, h0w, h0w + 4096, OFF_W1AH, OFF_W1AL, raA, raB, cbOff);
        gemm_dual(aA, aB, sb, h1r, h1r + 4096, OFF_W1BH, OFF_W1BL, raA, raB, cbOff);
        cell_s(aA, c1A, hA, ifh);
        cell_s(aB, c1B, hB, ifh);
        store_s(smem, h1w, h1w + 4096, hA, uo, rA, rB);
        store_s(smem, h1w, h1w + 4096, hB, uo, rA + 16, rB + 16);
        // no 2nd barrier: next step's barrier covers h1 visibility + WAR

        xv[0] = xn[0]; xv[1] = xn[1]; xv[2] = xn[2]; xv[3] = xn[3];
    }
    __syncthreads();

    // ---------- decoder weights ----------
    store_w(smem, OFF_W0H, OFF_W0L, dWhh0);
    store_w(smem, OFF_W1AH, OFF_W1AL, dWih1);
    store_w(smem, OFF_W1BH, OFF_W1BL, dWhh1);
    #pragma unroll
    for (int nt = 0; nt < 2; ++nt) {
        b0c[nt][0] = db0[cI[nt][0]]; b0c[nt][1] = db0[cI[nt][1]];
        b1c[nt][0] = db1[cI[nt][0]]; b1c[nt][1] = db1[cI[nt][1]];
        wic[nt][0] = dWih0[cI[nt][0]]; wic[nt][1] = dWih0[cI[nt][1]];
    }
    const float fcw = fcW[uo];
    const float fcbv = fcb[0];
    __syncthreads();

    // ---------- decoder: 7 autoregressive steps ----------
    float din[4] = {0.f, 0.f, 0.f, 0.f};
    for (int s = 0; s < HORIZON; ++s) {
        unsigned rp = (unsigned)((TT + s) & 1);
        unsigned h0r = OFF_AH0 + rp * 8192u, h0w = OFF_AH0 + (rp ^ 1) * 8192u;
        unsigned h1r = OFF_AH1 + rp * 8192u, h1w = OFF_AH1 + (rp ^ 1) * 8192u;

        float aA[2][4], aB[2][4];
        #pragma unroll
        for (int nt = 0; nt < 2; ++nt) {
            aA[nt][0] = fmaf(din[0], wic[nt][0], b0c[nt][0]);
            aA[nt][1] = fmaf(din[0], wic[nt][1], b0c[nt][1]);
            aA[nt][2] = fmaf(din[1], wic[nt][0], b0c[nt][0]);
            aA[nt][3] = fmaf(din[1], wic[nt][1], b0c[nt][1]);
            aB[nt][0] = fmaf(din[2], wic[nt][0], b0c[nt][0]);
            aB[nt][1] = fmaf(din[2], wic[nt][1], b0c[nt][1]);
            aB[nt][2] = fmaf(din[3], wic[nt][0], b0c[nt][0]);
            aB[nt][3] = fmaf(din[3], wic[nt][1], b0c[nt][1]);
        }
        gemm_dual(aA, aB, sb, h0r, h0r + 4096, OFF_W0H, OFF_W0L, raA, raB, cbOff);
        float hA[2], hB[2];
        cell_s(aA, c0A, hA, ifh);
        cell_s(aB, c0B, hB, ifh);
        store_s(smem, h0w, h0w + 4096, hA, uo, rA, rB);
        store_s(smem, h0w, h0w + 4096, hB, uo, rA + 16, rB + 16);
        __syncthreads();

        #pragma unroll
        for (int nt = 0; nt < 2; ++nt) {
            aA[nt][0] = b1c[nt][0]; aA[nt][1] = b1c[nt][1];
            aA[nt][2] = b1c[nt][0]; aA[nt][3] = b1c[nt][1];
            aB[nt][0] = b1c[nt][0]; aB[nt][1] = b1c[nt][1];
            aB[nt][2] = b1c[nt][0]; aB[nt][3] = b1c[nt][1];
        }
        gemm_dual(aA, aB, sb, h0w, h0w + 4096, OFF_W1AH, OFF_W1AL, raA, raB, cbOff);
        gemm_dual(aA, aB, sb, h1r, h1r + 4096, OFF_W1BH, OFF_W1BL, raA, raB, cbOff);
        cell_s(aA, c1A, hA, ifh);
        cell_s(aB, c1B, hB, ifh);
        store_s(smem, h1w, h1w + 4096, hA, uo, rA, rB);
        store_s(smem, h1w, h1w + 4096, hB, uo, rA + 16, rB + 16);

        // FC: each lane contributes its owned unit; quad shfl sums 4 units/warp
        float vA0 = hA[0] * fcw, vA1 = hA[1] * fcw;
        float vB0 = hB[0] * fcw, vB1 = hB[1] * fcw;
        vA0 += __shfl_xor_sync(0xFFFFFFFFu, vA0, 1);
        vA1 += __shfl_xor_sync(0xFFFFFFFFu, vA1, 1);
        vB0 += __shfl_xor_sync(0xFFFFFFFFu, vB0, 1);
        vB1 += __shfl_xor_sync(0xFFFFFFFFu, vB1, 1);
        vA0 += __shfl_xor_sync(0xFFFFFFFFu, vA0, 2);
        vA1 += __shfl_xor_sync(0xFFFFFFFFu, vA1, 2);
        vB0 += __shfl_xor_sync(0xFFFFFFFFu, vB0, 2);
        vB1 += __shfl_xor_sync(0xFFFFFFFFu, vB1, 2);
        if ((lane & 3) == 0) {
            g_pp[blk][jw][rA] = vA0;
            g_pp[blk][jw][rB] = vA1;
            g_pp[blk][jw][rA + 16] = vB0;
            g_pp[blk][jw][rB + 16] = vB1;
        }
        __syncthreads();
        if (tid < 32) {
            float sum = fcbv;
            #pragma unroll
            for (int j = 0; j < 16; ++j) sum += g_pp[blk][j][tid];
            out[(blk * 32 + tid) * HORIZON + s] = sum;
            g_fb[blk][tid] = sum;
        }
        __syncthreads();
        din[0] = g_fb[blk][rA];
        din[1] = g_fb[blk][rB];
        din[2] = g_fb[blk][rA + 16];
        din[3] = g_fb[blk][rB + 16];
    }
}

extern "C" void kernel_launch(void *const *d_in, const int *in_sizes, int n_in,
                              void *d_out, int out_size) {
    cudaFuncSetAttribute(lstm_kernel, cudaFuncAttributeMaxDynamicSharedMemorySize, SMEM_BYTES);
    lstm_kernel<<<NCTA, NTH, SMEM_BYTES>>>(
        (const float *)d_in[0],
        (const float *)d_in[1], (const float *)d_in[2], (const float *)d_in[3],
        (const float *)d_in[4], (const float *)d_in[5], (const float *)d_in[6],
        (const float *)d_in[7], (const float *)d_in[8], (const float *)d_in[9],
        (const float *)d_in[10], (const float *)d_in[11], (const float *)d_in[12],
        (const float *)d_in[13], (const float *)d_in[14],
        (float *)d_out);
}

// round 15
// speedup vs baseline: 1.5352x; 1.2807x over previous
#include <cuda_runtime.h>
#include <cuda_bf16.h>

#define BB 4096
#define TT 365
#define HORIZON 7
#define NCTA 128
#define NTH 512

// ---- SMEM byte offsets (all arrays 128B-row pitch, SW128 swizzled) ----
#define OFF_W0H   0u          // Whh0 hi   [256 cols][64 k] bf16
#define OFF_W0L   32768u      // Whh0 lo
#define OFF_W1AH  65536u      // Wih1 hi   (L1, k from h0)
#define OFF_W1AL  98304u
#define OFF_W1BH  131072u     // Whh1 hi   (L1, k from h1)
#define OFF_W1BL  163840u
#define OFF_AH0   196608u     // h0[buf 2]: 32x64 bf16 = 4096B each (h in plain bf16 now)
#define OFF_AH1   204800u     // h1[buf 2]
#define SMEM_BYTES 212992u

// decoder FC scratch (per-CTA slices of device globals; no allocation)
__device__ float g_pp[NCTA][16][32];
__device__ float g_fb[NCTA][32];

__device__ __forceinline__ unsigned swz(unsigned o) { return o ^ ((o >> 3) & 0x70u); }

__device__ __forceinline__ void ldsm4(unsigned &r0, unsigned &r1, unsigned &r2, unsigned &r3,
                                      unsigned a) {
    asm volatile("ldmatrix.sync.aligned.m8n8.x4.shared.b16 {%0,%1,%2,%3}, [%4];"
                 : "=r"(r0), "=r"(r1), "=r"(r2), "=r"(r3) : "r"(a));
}

__device__ __forceinline__ void mma16816(float d[4], unsigned a0, unsigned a1, unsigned a2,
                                         unsigned a3, unsigned b0, unsigned b1) {
    asm volatile("mma.sync.aligned.m16n8k16.row.col.f32.bf16.bf16.f32 "
                 "{%0,%1,%2,%3},{%4,%5,%6,%7},{%8,%9},{%0,%1,%2,%3};"
                 : "+f"(d[0]), "+f"(d[1]), "+f"(d[2]), "+f"(d[3])
                 : "r"(a0), "r"(a1), "r"(a2), "r"(a3), "r"(b0), "r"(b1));
}

__device__ __forceinline__ float sigm(float v) {
    return __fdividef(1.f, 1.f + __expf(-v));
}
__device__ __forceinline__ float tanh_(float v) {
    float a = fabsf(v);
    float e = __expf(-2.f * a);
    float r = __fdividef(1.f - e, 1.f + e);
    return copysignf(r, v);
}

// Dual-stream GEMM, 2-product split: acc += a_bf16 @ (W_hi + W_lo).
// h is plain bf16 (hi only); weights stay hi/lo split -> weight path near-fp32.
// W fragments loaded ONCE per ks, shared by both streams. m16n16 per stream.
__device__ __forceinline__ void gemm_dual(float accA[2][4], float accB[2][4], unsigned sb,
                                          unsigned aH,
                                          unsigned wH, unsigned wL,
                                          unsigned raA, unsigned raB, unsigned cbOff) {
    #pragma unroll
    for (int ks = 0; ks < 4; ++ks) {
        unsigned bh0, bh1, bh2, bh3, bl0, bl1, bl2, bl3;
        ldsm4(bh0, bh1, bh2, bh3, sb + wH + swz(cbOff + ks * 32));
        ldsm4(bl0, bl1, bl2, bl3, sb + wL + swz(cbOff + ks * 32));
        unsigned a0, a1, a2, a3;
        ldsm4(a0, a1, a2, a3, sb + aH + swz(raA + ks * 32));
        mma16816(accA[0], a0, a1, a2, a3, bh0, bh1);
        mma16816(accA[0], a0, a1, a2, a3, bl0, bl1);
        mma16816(accA[1], a0, a1, a2, a3, bh2, bh3);
        mma16816(accA[1], a0, a1, a2, a3, bl2, bl3);
        unsigned c0, c1, c2, c3;
        ldsm4(c0, c1, c2, c3, sb + aH + swz(raB + ks * 32));
        mma16816(accB[0], c0, c1, c2, c3, bh0, bh1);
        mma16816(accB[0], c0, c1, c2, c3, bl0, bl1);
        mma16816(accB[1], c0, c1, c2, c3, bh2, bh3);
        mma16816(accB[1], c0, c1, c2, c3, bl2, bl3);
    }
}

// Per-stream split cell: even lane owns tile 0 (its unit), odd owns tile 1.
// 4 shfl. hvo[row 0/1] = h of owned unit at rows rA, rB. cst[2] likewise.
__device__ __forceinline__ void cell_s(const float acc[2][4], float cst[2],
                                       float hvo[2], int ifh) {
    float recv[4];
    #pragma unroll
    for (int e = 0; e < 4; ++e) {
        float send = ifh ? acc[1][e] : acc[0][e];
        recv[e] = __shfl_xor_sync(0xFFFFFFFFu, send, 1);
    }
    const float *own = ifh ? acc[0] : acc[1];
    float gi = ifh ? own[0] : recv[0];
    float gf = ifh ? own[1] : recv[1];
    float gg = ifh ? recv[0] : own[0];
    float go = ifh ? recv[1] : own[1];
    float cn = sigm(gf) * cst[0] + sigm(gi) * tanh_(gg);
    cst[0] = cn;
    hvo[0] = sigm(go) * tanh_(cn);
    gi = ifh ? own[2] : recv[2];
    gf = ifh ? own[3] : recv[3];
    gg = ifh ? recv[2] : own[2];
    go = ifh ? recv[3] : own[3];
    cn = sigm(gf) * cst[1] + sigm(gi) * tanh_(gg);
    cst[1] = cn;
    hvo[1] = sigm(go) * tanh_(cn);
}

// Store owned unit's h (plain bf16) for rows rA, rB.
__device__ __forceinline__ void store_s(char *smp, unsigned offH,
                                        const float hvo[2], int uo, int rA, int rB) {
    unsigned oA = swz((unsigned)(rA * 128 + uo * 2));
    unsigned oB = swz((unsigned)(rB * 128 + uo * 2));
    *(__nv_bfloat16 *)(smp + offH + oA) = __float2bfloat16(hvo[0]);
    *(__nv_bfloat16 *)(smp + offH + oB) = __float2bfloat16(hvo[1]);
}

// Split-store raw fp32 weights [256 gate-rows][64 k] into gate-interleaved
// swizzled bf16 hi/lo: col c = u*4 + g, addr = swz(c*128 + k*2).
__device__ void store_w(char *smp, unsigned offH, unsigned offL, const float *__restrict__ raw) {
    for (int e = threadIdx.x; e < 256 * 64; e += NTH) {
        int R = e >> 6, k = e & 63;
        int c = (R & 63) * 4 + (R >> 6);
        float w = raw[e];
        __nv_bfloat16 hi = __float2bfloat16(w);
        __nv_bfloat16 lo = __float2bfloat16(w - __bfloat162float(hi));
        unsigned o = swz((unsigned)(c * 128 + k * 2));
        *(__nv_bfloat16 *)(smp + offH + o) = hi;
        *(__nv_bfloat16 *)(smp + offL + o) = lo;
    }
}

__global__ void __launch_bounds__(NTH, 1)
lstm_kernel(const float *__restrict__ x,
            const float *__restrict__ eWih0, const float *__restrict__ eWhh0,
            const float *__restrict__ eb0,
            const float *__restrict__ eWih1, const float *__restrict__ eWhh1,
            const float *__restrict__ eb1,
            const float *__restrict__ dWih0, const float *__restrict__ dWhh0,
            const float *__restrict__ db0,
            const float *__restrict__ dWih1, const float *__restrict__ dWhh1,
            const float *__restrict__ db1,
            const float *__restrict__ fcW, const float *__restrict__ fcb,
            float *__restrict__ out) {
    extern __shared__ char smem[];
    unsigned sb = (unsigned)__cvta_generic_to_shared(smem);

    const int tid = threadIdx.x;
    const int lane = tid & 31;
    const int jw = tid >> 5;           // warp = n16 block: units 4jw..4jw+3
    const int blk = blockIdx.x;

    const int ifh = !(lane & 1);       // even lane holds (i,f); odd (g,o)
    const int rA = lane >> 2;          // stream-local rows rA, rA+8
    const int rB = rA + 8;
    const int uo = 4 * jw + (ifh ? ((lane >> 1) & 1) : 2 + ((lane >> 1) & 1));

    const unsigned raA = (unsigned)(((lane & 7) + (lane & 8)) * 128 + ((lane >> 4) & 1) * 16);
    const unsigned raB = raA + 16 * 128;
    const unsigned cbOff = (unsigned)((16 * jw + (lane & 7) + 8 * ((lane >> 4) & 1)) * 128
                                      + ((lane >> 3) & 1) * 16);

    int cI[2][2];
    #pragma unroll
    for (int nt = 0; nt < 2; ++nt) {
        int c0 = 16 * jw + 8 * nt + ((lane & 3) << 1);
        cI[nt][0] = (c0 & 3) * 64 + (c0 >> 2);
        cI[nt][1] = ((c0 + 1) & 3) * 64 + ((c0 + 1) >> 2);
    }

    // ---------- encoder weights ----------
    store_w(smem, OFF_W0H, OFF_W0L, eWhh0);
    store_w(smem, OFF_W1AH, OFF_W1AL, eWih1);
    store_w(smem, OFF_W1BH, OFF_W1BL, eWhh1);
    for (int i = tid; i < 4096; i += NTH) ((float *)(smem + OFF_AH0))[i] = 0.f;  // 16KB h bufs

    float b0c[2][2], b1c[2][2], wic[2][2];
    #pragma unroll
    for (int nt = 0; nt < 2; ++nt) {
        b0c[nt][0] = eb0[cI[nt][0]]; b0c[nt][1] = eb0[cI[nt][1]];
        b1c[nt][0] = eb1[cI[nt][0]]; b1c[nt][1] = eb1[cI[nt][1]];
        wic[nt][0] = eWih0[cI[nt][0]]; wic[nt][1] = eWih0[cI[nt][1]];
    }
    __syncthreads();

    float c0A[2] = {0.f, 0.f}, c0B[2] = {0.f, 0.f};
    float c1A[2] = {0.f, 0.f}, c1B[2] = {0.f, 0.f};

    const float *xbase = x + blk * 32 * TT;
    float xv[4];
    xv[0] = xbase[rA * TT];
    xv[1] = xbase[rB * TT];
    xv[2] = xbase[(rA + 16) * TT];
    xv[3] = xbase[(rB + 16) * TT];

    // ---------- encoder: 365 steps, 1 barrier/step, dual-stream ILP ----------
    for (int t = 0; t < TT; ++t) {
        float xn[4] = {0.f, 0.f, 0.f, 0.f};
        if (t + 1 < TT) {
            xn[0] = xbase[rA * TT + t + 1];
            xn[1] = xbase[rB * TT + t + 1];
            xn[2] = xbase[(rA + 16) * TT + t + 1];
            xn[3] = xbase[(rB + 16) * TT + t + 1];
        }
        unsigned h0r = OFF_AH0 + (unsigned)(t & 1) * 4096u;
        unsigned h0w = OFF_AH0 + (unsigned)((t + 1) & 1) * 4096u;
        unsigned h1r = OFF_AH1 + (unsigned)(t & 1) * 4096u;
        unsigned h1w = OFF_AH1 + (unsigned)((t + 1) & 1) * 4096u;

        // phase 1: layer 0 for both streams
        float aA[2][4], aB[2][4];
        #pragma unroll
        for (int nt = 0; nt < 2; ++nt) {
            aA[nt][0] = fmaf(xv[0], wic[nt][0], b0c[nt][0]);
            aA[nt][1] = fmaf(xv[0], wic[nt][1], b0c[nt][1]);
            aA[nt][2] = fmaf(xv[1], wic[nt][0], b0c[nt][0]);
            aA[nt][3] = fmaf(xv[1], wic[nt][1], b0c[nt][1]);
            aB[nt][0] = fmaf(xv[2], wic[nt][0], b0c[nt][0]);
            aB[nt][1] = fmaf(xv[2], wic[nt][1], b0c[nt][1]);
            aB[nt][2] = fmaf(xv[3], wic[nt][0], b0c[nt][0]);
            aB[nt][3] = fmaf(xv[3], wic[nt][1], b0c[nt][1]);
        }
        gemm_dual(aA, aB, sb, h0r, OFF_W0H, OFF_W0L, raA, raB, cbOff);
        float hA[2], hB[2];
        cell_s(aA, c0A, hA, ifh);
        cell_s(aB, c0B, hB, ifh);
        store_s(smem, h0w, hA, uo, rA, rB);
        store_s(smem, h0w, hB, uo, rA + 16, rB + 16);
        __syncthreads();

        // phase 2: layer 1 for both streams (K=128: h0_cur + h1_prev)
        #pragma unroll
        for (int nt = 0; nt < 2; ++nt) {
            aA[nt][0] = b1c[nt][0]; aA[nt][1] = b1c[nt][1];
            aA[nt][2] = b1c[nt][0]; aA[nt][3] = b1c[nt][1];
            aB[nt][0] = b1c[nt][0]; aB[nt][1] = b1c[nt][1];
            aB[nt][2] = b1c[nt][0]; aB[nt][3] = b1c[nt][1];
        }
        gemm_dual(aA, aB, sb, h0w, OFF_W1AH, OFF_W1AL, raA, raB, cbOff);
        gemm_dual(aA, aB, sb, h1r, OFF_W1BH, OFF_W1BL, raA, raB, cbOff);
        cell_s(aA, c1A, hA, ifh);
        cell_s(aB, c1B, hB, ifh);
        store_s(smem, h1w, hA, uo, rA, rB);
        store_s(smem, h1w, hB, uo, rA + 16, rB + 16);
        // no 2nd barrier: next step's barrier covers h1 visibility + WAR

        xv[0] = xn[0]; xv[1] = xn[1]; xv[2] = xn[2]; xv[3] = xn[3];
    }
    __syncthreads();

    // ---------- decoder weights ----------
    store_w(smem, OFF_W0H, OFF_W0L, dWhh0);
    store_w(smem, OFF_W1AH, OFF_W1AL, dWih1);
    store_w(smem, OFF_W1BH, OFF_W1BL, dWhh1);
    #pragma unroll
    for (int nt = 0; nt < 2; ++nt) {
        b0c[nt][0] = db0[cI[nt][0]]; b0c[nt][1] = db0[cI[nt][1]];
        b1c[nt][0] = db1[cI[nt][0]]; b1c[nt][1] = db1[cI[nt][1]];
        wic[nt][0] = dWih0[cI[nt][0]]; wic[nt][1] = dWih0[cI[nt][1]];
    }
    const float fcw = fcW[uo];
    const float fcbv = fcb[0];
    __syncthreads();

    // ---------- decoder: 7 autoregressive steps ----------
    float din[4] = {0.f, 0.f, 0.f, 0.f};
    for (int s = 0; s < HORIZON; ++s) {
        unsigned rp = (unsigned)((TT + s) & 1);
        unsigned h0r = OFF_AH0 + rp * 4096u, h0w = OFF_AH0 + (rp ^ 1) * 4096u;
        unsigned h1r = OFF_AH1 + rp * 4096u, h1w = OFF_AH1 + (rp ^ 1) * 4096u;

        float aA[2][4], aB[2][4];
        #pragma unroll
        for (int nt = 0; nt < 2; ++nt) {
            aA[nt][0] = fmaf(din[0], wic[nt][0], b0c[nt][0]);
            aA[nt][1] = fmaf(din[0], wic[nt][1], b0c[nt][1]);
            aA[nt][2] = fmaf(din[1], wic[nt][0], b0c[nt][0]);
            aA[nt][3] = fmaf(din[1], wic[nt][1], b0c[nt][1]);
            aB[nt][0] = fmaf(din[2], wic[nt][0], b0c[nt][0]);
            aB[nt][1] = fmaf(din[2], wic[nt][1], b0c[nt][1]);
            aB[nt][2] = fmaf(din[3], wic[nt][0], b0c[nt][0]);
            aB[nt][3] = fmaf(din[3], wic[nt][1], b0c[nt][1]);
        }
        gemm_dual(aA, aB, sb, h0r, OFF_W0H, OFF_W0L, raA, raB, cbOff);
        float hA[2], hB[2];
        cell_s(aA, c0A, hA, ifh);
        cell_s(aB, c0B, hB, ifh);
        store_s(smem, h0w, hA, uo, rA, rB);
        store_s(smem, h0w, hB, uo, rA + 16, rB + 16);
        __syncthreads();

        #pragma unroll
        for (int nt = 0; nt < 2; ++nt) {
            aA[nt][0] = b1c[nt][0]; aA[nt][1] = b1c[nt][1];
            aA[nt][2] = b1c[nt][0]; aA[nt][3] = b1c[nt][1];
            aB[nt][0] = b1c[nt][0]; aB[nt][1] = b1c[nt][1];
            aB[nt][2] = b1c[nt][0]; aB[nt][3] = b1c[nt][1];
        }
        gemm_dual(aA, aB, sb, h0w, OFF_W1AH, OFF_W1AL, raA, raB, cbOff);
        gemm_dual(aA, aB, sb, h1r, OFF_W1BH, OFF_W1BL, raA, raB, cbOff);
        cell_s(aA, c1A, hA, ifh);
        cell_s(aB, c1B, hB, ifh);
        store_s(smem, h1w, hA, uo, rA, rB);
        store_s(smem, h1w, hB, uo, rA + 16, rB + 16);

        // FC: each lane contributes its owned unit; quad shfl sums 4 units/warp
        float vA0 = hA[0] * fcw, vA1 = hA[1] * fcw;
        float vB0 = hB[0] * fcw, vB1 = hB[1] * fcw;
        vA0 += __shfl_xor_sync(0xFFFFFFFFu, vA0, 1);
        vA1 += __shfl_xor_sync(0xFFFFFFFFu, vA1, 1);
        vB0 += __shfl_xor_sync(0xFFFFFFFFu, vB0, 1);
        vB1 += __shfl_xor_sync(0xFFFFFFFFu, vB1, 1);
        vA0 += __shfl_xor_sync(0xFFFFFFFFu, vA0, 2);
        vA1 += __shfl_xor_sync(0xFFFFFFFFu, vA1, 2);
        vB0 += __shfl_xor_sync(0xFFFFFFFFu, vB0, 2);
        vB1 += __shfl_xor_sync(0xFFFFFFFFu, vB1, 2);
        if ((lane & 3) == 0) {
            g_pp[blk][jw][rA] = vA0;
            g_pp[blk][jw][rB] = vA1;
            g_pp[blk][jw][rA + 16] = vB0;
            g_pp[blk][jw][rB + 16] = vB1;
        }
        __syncthreads();
        if (tid < 32) {
            float sum = fcbv;
            #pragma unroll
            for (int j = 0; j < 16; ++j) sum += g_pp[blk][j][tid];
            out[(blk * 32 + tid) * HORIZON + s] = sum;
            g_fb[blk][tid] = sum;
        }
        __syncthreads();
        din[0] = g_fb[blk][rA];
        din[1] = g_fb[blk][rB];
        din[2] = g_fb[blk][rA + 16];
        din[3] = g_fb[blk][rB + 16];
    }
}

extern "C" void kernel_launch(void *const *d_in, const int *in_sizes, int n_in,
                              void *d_out, int out_size) {
    cudaFuncSetAttribute(lstm_kernel, cudaFuncAttributeMaxDynamicSharedMemorySize, SMEM_BYTES);
    lstm_kernel<<<NCTA, NTH, SMEM_BYTES>>>(
        (const float *)d_in[0],
        (const float *)d_in[1], (const float *)d_in[2], (const float *)d_in[3],
        (const float *)d_in[4], (const float *)d_in[5], (const float *)d_in[6],
        (const float *)d_in[7], (const float *)d_in[8], (const float *)d_in[9],
        (const float *)d_in[10], (const float *)d_in[11], (const float *)d_in[12],
        (const float *)d_in[13], (const float *)d_in[14],
        (float *)d_out);
}

// round 16
// speedup vs baseline: 1.8593x; 1.2111x over previous
#include <cuda_runtime.h>
#include <cuda_bf16.h>

#define BB 4096
#define TT 365
#define HORIZON 7
#define NCTA 128
#define NTH 512

// ---- SMEM byte offsets (all arrays 128B-row pitch, SW128 swizzled) ----
#define OFF_W0    0u          // Whh0 [256 cols][64 k] bf16
#define OFF_W1A   32768u      // Wih1 (L1, k from h0)
#define OFF_W1B   65536u      // Whh1 (L1, k from h1)
#define OFF_AH0   98304u      // h0[buf 2]: 32x64 bf16 = 4096B each
#define OFF_AH1   106496u     // h1[buf 2]
#define SMEM_BYTES 114688u

// decoder FC scratch (per-CTA slices of device globals; no allocation)
__device__ float g_pp[NCTA][16][32];
__device__ float g_fb[NCTA][32];

__device__ __forceinline__ unsigned swz(unsigned o) { return o ^ ((o >> 3) & 0x70u); }

__device__ __forceinline__ void ldsm4(unsigned &r0, unsigned &r1, unsigned &r2, unsigned &r3,
                                      unsigned a) {
    asm volatile("ldmatrix.sync.aligned.m8n8.x4.shared.b16 {%0,%1,%2,%3}, [%4];"
                 : "=r"(r0), "=r"(r1), "=r"(r2), "=r"(r3) : "r"(a));
}

__device__ __forceinline__ void mma16816(float d[4], unsigned a0, unsigned a1, unsigned a2,
                                         unsigned a3, unsigned b0, unsigned b1) {
    asm volatile("mma.sync.aligned.m16n8k16.row.col.f32.bf16.bf16.f32 "
                 "{%0,%1,%2,%3},{%4,%5,%6,%7},{%8,%9},{%0,%1,%2,%3};"
                 : "+f"(d[0]), "+f"(d[1]), "+f"(d[2]), "+f"(d[3])
                 : "r"(a0), "r"(a1), "r"(a2), "r"(a3), "r"(b0), "r"(b1));
}

__device__ __forceinline__ float sigm(float v) {
    return __fdividef(1.f, 1.f + __expf(-v));
}
__device__ __forceinline__ float tanh_(float v) {
    float a = fabsf(v);
    float e = __expf(-2.f * a);
    float r = __fdividef(1.f - e, 1.f + e);
    return copysignf(r, v);
}

// Dual-stream GEMM, pure bf16: acc += a_bf16 @ W_bf16 (fp32 accumulate).
// W fragments loaded ONCE per ks, shared by both streams. m16n16 per stream.
__device__ __forceinline__ void gemm_dual(float accA[2][4], float accB[2][4], unsigned sb,
                                          unsigned aH, unsigned wB,
                                          unsigned raA, unsigned raB, unsigned cbOff) {
    #pragma unroll
    for (int ks = 0; ks < 4; ++ks) {
        unsigned bh0, bh1, bh2, bh3;
        ldsm4(bh0, bh1, bh2, bh3, sb + wB + swz(cbOff + ks * 32));
        unsigned a0, a1, a2, a3;
        ldsm4(a0, a1, a2, a3, sb + aH + swz(raA + ks * 32));
        mma16816(accA[0], a0, a1, a2, a3, bh0, bh1);
        mma16816(accA[1], a0, a1, a2, a3, bh2, bh3);
        unsigned c0, c1, c2, c3;
        ldsm4(c0, c1, c2, c3, sb + aH + swz(raB + ks * 32));
        mma16816(accB[0], c0, c1, c2, c3, bh0, bh1);
        mma16816(accB[1], c0, c1, c2, c3, bh2, bh3);
    }
}

// Per-stream split cell: even lane owns tile 0 (its unit), odd owns tile 1.
// 4 shfl. hvo[row 0/1] = h of owned unit at rows rA, rB. cst[2] likewise.
__device__ __forceinline__ void cell_s(const float acc[2][4], float cst[2],
                                       float hvo[2], int ifh) {
    float recv[4];
    #pragma unroll
    for (int e = 0; e < 4; ++e) {
        float send = ifh ? acc[1][e] : acc[0][e];
        recv[e] = __shfl_xor_sync(0xFFFFFFFFu, send, 1);
    }
    const float *own = ifh ? acc[0] : acc[1];
    float gi = ifh ? own[0] : recv[0];
    float gf = ifh ? own[1] : recv[1];
    float gg = ifh ? recv[0] : own[0];
    float go = ifh ? recv[1] : own[1];
    float cn = sigm(gf) * cst[0] + sigm(gi) * tanh_(gg);
    cst[0] = cn;
    hvo[0] = sigm(go) * tanh_(cn);
    gi = ifh ? own[2] : recv[2];
    gf = ifh ? own[3] : recv[3];
    gg = ifh ? recv[2] : own[2];
    go = ifh ? recv[3] : own[3];
    cn = sigm(gf) * cst[1] + sigm(gi) * tanh_(gg);
    cst[1] = cn;
    hvo[1] = sigm(go) * tanh_(cn);
}

// Store owned unit's h (bf16) for rows rA, rB.
__device__ __forceinline__ void store_s(char *smp, unsigned offH,
                                        const float hvo[2], int uo, int rA, int rB) {
    unsigned oA = swz((unsigned)(rA * 128 + uo * 2));
    unsigned oB = swz((unsigned)(rB * 128 + uo * 2));
    *(__nv_bfloat16 *)(smp + offH + oA) = __float2bfloat16(hvo[0]);
    *(__nv_bfloat16 *)(smp + offH + oB) = __float2bfloat16(hvo[1]);
}

// Store raw fp32 weights [256 gate-rows][64 k] into gate-interleaved
// swizzled bf16: col c = u*4 + g, addr = swz(c*128 + k*2).
__device__ void store_w(char *smp, unsigned off, const float *__restrict__ raw) {
    for (int e = threadIdx.x; e < 256 * 64; e += NTH) {
        int R = e >> 6, k = e & 63;
        int c = (R & 63) * 4 + (R >> 6);
        unsigned o = swz((unsigned)(c * 128 + k * 2));
        *(__nv_bfloat16 *)(smp + off + o) = __float2bfloat16(raw[e]);
    }
}

__global__ void __launch_bounds__(NTH, 1)
lstm_kernel(const float *__restrict__ x,
            const float *__restrict__ eWih0, const float *__restrict__ eWhh0,
            const float *__restrict__ eb0,
            const float *__restrict__ eWih1, const float *__restrict__ eWhh1,
            const float *__restrict__ eb1,
            const float *__restrict__ dWih0, const float *__restrict__ dWhh0,
            const float *__restrict__ db0,
            const float *__restrict__ dWih1, const float *__restrict__ dWhh1,
            const float *__restrict__ db1,
            const float *__restrict__ fcW, const float *__restrict__ fcb,
            float *__restrict__ out) {
    extern __shared__ char smem[];
    unsigned sb = (unsigned)__cvta_generic_to_shared(smem);

    const int tid = threadIdx.x;
    const int lane = tid & 31;
    const int jw = tid >> 5;           // warp = n16 block: units 4jw..4jw+3
    const int blk = blockIdx.x;

    const int ifh = !(lane & 1);       // even lane holds (i,f); odd (g,o)
    const int rA = lane >> 2;          // stream-local rows rA, rA+8
    const int rB = rA + 8;
    const int uo = 4 * jw + (ifh ? ((lane >> 1) & 1) : 2 + ((lane >> 1) & 1));

    const unsigned raA = (unsigned)(((lane & 7) + (lane & 8)) * 128 + ((lane >> 4) & 1) * 16);
    const unsigned raB = raA + 16 * 128;
    const unsigned cbOff = (unsigned)((16 * jw + (lane & 7) + 8 * ((lane >> 4) & 1)) * 128
                                      + ((lane >> 3) & 1) * 16);

    int cI[2][2];
    #pragma unroll
    for (int nt = 0; nt < 2; ++nt) {
        int c0 = 16 * jw + 8 * nt + ((lane & 3) << 1);
        cI[nt][0] = (c0 & 3) * 64 + (c0 >> 2);
        cI[nt][1] = ((c0 + 1) & 3) * 64 + ((c0 + 1) >> 2);
    }

    // ---------- encoder weights ----------
    store_w(smem, OFF_W0, eWhh0);
    store_w(smem, OFF_W1A, eWih1);
    store_w(smem, OFF_W1B, eWhh1);
    for (int i = tid; i < 4096; i += NTH) ((float *)(smem + OFF_AH0))[i] = 0.f;  // 16KB h bufs

    float b0c[2][2], b1c[2][2], wic[2][2];
    #pragma unroll
    for (int nt = 0; nt < 2; ++nt) {
        b0c[nt][0] = eb0[cI[nt][0]]; b0c[nt][1] = eb0[cI[nt][1]];
        b1c[nt][0] = eb1[cI[nt][0]]; b1c[nt][1] = eb1[cI[nt][1]];
        wic[nt][0] = eWih0[cI[nt][0]]; wic[nt][1] = eWih0[cI[nt][1]];
    }
    __syncthreads();

    float c0A[2] = {0.f, 0.f}, c0B[2] = {0.f, 0.f};
    float c1A[2] = {0.f, 0.f}, c1B[2] = {0.f, 0.f};

    const float *xbase = x + blk * 32 * TT;
    float xv[4];
    xv[0] = xbase[rA * TT];
    xv[1] = xbase[rB * TT];
    xv[2] = xbase[(rA + 16) * TT];
    xv[3] = xbase[(rB + 16) * TT];

    // ---------- encoder: 365 steps, 1 barrier/step, dual-stream ILP ----------
    for (int t = 0; t < TT; ++t) {
        float xn[4] = {0.f, 0.f, 0.f, 0.f};
        if (t + 1 < TT) {
            xn[0] = xbase[rA * TT + t + 1];
            xn[1] = xbase[rB * TT + t + 1];
            xn[2] = xbase[(rA + 16) * TT + t + 1];
            xn[3] = xbase[(rB + 16) * TT + t + 1];
        }
        unsigned h0r = OFF_AH0 + (unsigned)(t & 1) * 4096u;
        unsigned h0w = OFF_AH0 + (unsigned)((t + 1) & 1) * 4096u;
        unsigned h1r = OFF_AH1 + (unsigned)(t & 1) * 4096u;
        unsigned h1w = OFF_AH1 + (unsigned)((t + 1) & 1) * 4096u;

        // phase 1: layer 0 for both streams
        float aA[2][4], aB[2][4];
        #pragma unroll
        for (int nt = 0; nt < 2; ++nt) {
            aA[nt][0] = fmaf(xv[0], wic[nt][0], b0c[nt][0]);
            aA[nt][1] = fmaf(xv[0], wic[nt][1], b0c[nt][1]);
            aA[nt][2] = fmaf(xv[1], wic[nt][0], b0c[nt][0]);
            aA[nt][3] = fmaf(xv[1], wic[nt][1], b0c[nt][1]);
            aB[nt][0] = fmaf(xv[2], wic[nt][0], b0c[nt][0]);
            aB[nt][1] = fmaf(xv[2], wic[nt][1], b0c[nt][1]);
            aB[nt][2] = fmaf(xv[3], wic[nt][0], b0c[nt][0]);
            aB[nt][3] = fmaf(xv[3], wic[nt][1], b0c[nt][1]);
        }
        gemm_dual(aA, aB, sb, h0r, OFF_W0, raA, raB, cbOff);
        float hA[2], hB[2];
        cell_s(aA, c0A, hA, ifh);
        cell_s(aB, c0B, hB, ifh);
        store_s(smem, h0w, hA, uo, rA, rB);
        store_s(smem, h0w, hB, uo, rA + 16, rB + 16);
        __syncthreads();

        // phase 2: layer 1 for both streams (K=128: h0_cur + h1_prev)
        #pragma unroll
        for (int nt = 0; nt < 2; ++nt) {
            aA[nt][0] = b1c[nt][0]; aA[nt][1] = b1c[nt][1];
            aA[nt][2] = b1c[nt][0]; aA[nt][3] = b1c[nt][1];
            aB[nt][0] = b1c[nt][0]; aB[nt][1] = b1c[nt][1];
            aB[nt][2] = b1c[nt][0]; aB[nt][3] = b1c[nt][1];
        }
        gemm_dual(aA, aB, sb, h0w, OFF_W1A, raA, raB, cbOff);
        gemm_dual(aA, aB, sb, h1r, OFF_W1B, raA, raB, cbOff);
        cell_s(aA, c1A, hA, ifh);
        cell_s(aB, c1B, hB, ifh);
        store_s(smem, h1w, hA, uo, rA, rB);
        store_s(smem, h1w, hB, uo, rA + 16, rB + 16);
        // no 2nd barrier: next step's barrier covers h1 visibility + WAR

        xv[0] = xn[0]; xv[1] = xn[1]; xv[2] = xn[2]; xv[3] = xn[3];
    }
    __syncthreads();

    // ---------- decoder weights ----------
    store_w(smem, OFF_W0, dWhh0);
    store_w(smem, OFF_W1A, dWih1);
    store_w(smem, OFF_W1B, dWhh1);
    #pragma unroll
    for (int nt = 0; nt < 2; ++nt) {
        b0c[nt][0] = db0[cI[nt][0]]; b0c[nt][1] = db0[cI[nt][1]];
        b1c[nt][0] = db1[cI[nt][0]]; b1c[nt][1] = db1[cI[nt][1]];
        wic[nt][0] = dWih0[cI[nt][0]]; wic[nt][1] = dWih0[cI[nt][1]];
    }
    const float fcw = fcW[uo];
    const float fcbv = fcb[0];
    __syncthreads();

    // ---------- decoder: 7 autoregressive steps ----------
    float din[4] = {0.f, 0.f, 0.f, 0.f};
    for (int s = 0; s < HORIZON; ++s) {
        unsigned rp = (unsigned)((TT + s) & 1);
        unsigned h0r = OFF_AH0 + rp * 4096u, h0w = OFF_AH0 + (rp ^ 1) * 4096u;
        unsigned h1r = OFF_AH1 + rp * 4096u, h1w = OFF_AH1 + (rp ^ 1) * 4096u;

        float aA[2][4], aB[2][4];
        #pragma unroll
        for (int nt = 0; nt < 2; ++nt) {
            aA[nt][0] = fmaf(din[0], wic[nt][0], b0c[nt][0]);
            aA[nt][1] = fmaf(din[0], wic[nt][1], b0c[nt][1]);
            aA[nt][2] = fmaf(din[1], wic[nt][0], b0c[nt][0]);
            aA[nt][3] = fmaf(din[1], wic[nt][1], b0c[nt][1]);
            aB[nt][0] = fmaf(din[2], wic[nt][0], b0c[nt][0]);
            aB[nt][1] = fmaf(din[2], wic[nt][1], b0c[nt][1]);
            aB[nt][2] = fmaf(din[3], wic[nt][0], b0c[nt][0]);
            aB[nt][3] = fmaf(din[3], wic[nt][1], b0c[nt][1]);
        }
        gemm_dual(aA, aB, sb, h0r, OFF_W0, raA, raB, cbOff);
        float hA[2], hB[2];
        cell_s(aA, c0A, hA, ifh);
        cell_s(aB, c0B, hB, ifh);
        store_s(smem, h0w, hA, uo, rA, rB);
        store_s(smem, h0w, hB, uo, rA + 16, rB + 16);
        __syncthreads();

        #pragma unroll
        for (int nt = 0; nt < 2; ++nt) {
            aA[nt][0] = b1c[nt][0]; aA[nt][1] = b1c[nt][1];
            aA[nt][2] = b1c[nt][0]; aA[nt][3] = b1c[nt][1];
            aB[nt][0] = b1c[nt][0]; aB[nt][1] = b1c[nt][1];
            aB[nt][2] = b1c[nt][0]; aB[nt][3] = b1c[nt][1];
        }
        gemm_dual(aA, aB, sb, h0w, OFF_W1A, raA, raB, cbOff);
        gemm_dual(aA, aB, sb, h1r, OFF_W1B, raA, raB, cbOff);
        cell_s(aA, c1A, hA, ifh);
        cell_s(aB, c1B, hB, ifh);
        store_s(smem, h1w, hA, uo, rA, rB);
        store_s(smem, h1w, hB, uo, rA + 16, rB + 16);

        // FC: each lane contributes its owned unit; quad shfl sums 4 units/warp
        float vA0 = hA[0] * fcw, vA1 = hA[1] * fcw;
        float vB0 = hB[0] * fcw, vB1 = hB[1] * fcw;
        vA0 += __shfl_xor_sync(0xFFFFFFFFu, vA0, 1);
        vA1 += __shfl_xor_sync(0xFFFFFFFFu, vA1, 1);
        vB0 += __shfl_xor_sync(0xFFFFFFFFu, vB0, 1);
        vB1 += __shfl_xor_sync(0xFFFFFFFFu, vB1, 1);
        vA0 += __shfl_xor_sync(0xFFFFFFFFu, vA0, 2);
        vA1 += __shfl_xor_sync(0xFFFFFFFFu, vA1, 2);
        vB0 += __shfl_xor_sync(0xFFFFFFFFu, vB0, 2);
        vB1 += __shfl_xor_sync(0xFFFFFFFFu, vB1, 2);
        if ((lane & 3) == 0) {
            g_pp[blk][jw][rA] = vA0;
            g_pp[blk][jw][rB] = vA1;
            g_pp[blk][jw][rA + 16] = vB0;
            g_pp[blk][jw][rB + 16] = vB1;
        }
        __syncthreads();
        if (tid < 32) {
            float sum = fcbv;
            #pragma unroll
            for (int j = 0; j < 16; ++j) sum += g_pp[blk][j][tid];
            out[(blk * 32 + tid) * HORIZON + s] = sum;
            g_fb[blk][tid] = sum;
        }
        __syncthreads();
        din[0] = g_fb[blk][rA];
        din[1] = g_fb[blk][rB];
        din[2] = g_fb[blk][rA + 16];
        din[3] = g_fb[blk][rB + 16];
    }
}

extern "C" void kernel_launch(void *const *d_in, const int *in_sizes, int n_in,
                              void *d_out, int out_size) {
    cudaFuncSetAttribute(lstm_kernel, cudaFuncAttributeMaxDynamicSharedMemorySize, SMEM_BYTES);
    lstm_kernel<<<NCTA, NTH, SMEM_BYTES>>>(
        (const float *)d_in[0],
        (const float *)d_in[1], (const float *)d_in[2], (const float *)d_in[3],
        (const float *)d_in[4], (const float *)d_in[5], (const float *)d_in[6],
        (const float *)d_in[7], (const float *)d_in[8], (const float *)d_in[9],
        (const float *)d_in[10], (const float *)d_in[11], (const float *)d_in[12],
        (const float *)d_in[13], (const float *)d_in[14],
        (float *)d_out);
}

// round 17
// speedup vs baseline: 2.8405x; 1.5277x over previous
#include <cuda_runtime.h>
#include <cuda_bf16.h>

#define BB 4096
#define TT 365
#define HORIZON 7
#define NCTA 128
#define NTH 512

// ---- SMEM byte offsets (all arrays 128B-row pitch, SW128 swizzled) ----
#define OFF_W0    0u          // Whh0 [256 cols][64 k] bf16 (gate-per-lane interleave)
#define OFF_W1A   32768u      // Wih1 (L1, k from h0)
#define OFF_W1B   65536u      // Whh1 (L1, k from h1)
#define OFF_AH0   98304u      // h0[buf 2]: 32x64 bf16 = 4096B each
#define OFF_AH1   106496u     // h1[buf 2]
#define SMEM_BYTES 114688u

// decoder FC scratch (per-CTA slices of device globals; no allocation)
__device__ float g_pp[NCTA][16][32];
__device__ float g_fb[NCTA][32];

__device__ __forceinline__ unsigned swz(unsigned o) { return o ^ ((o >> 3) & 0x70u); }

__device__ __forceinline__ void ldsm4(unsigned &r0, unsigned &r1, unsigned &r2, unsigned &r3,
                                      unsigned a) {
    asm volatile("ldmatrix.sync.aligned.m8n8.x4.shared.b16 {%0,%1,%2,%3}, [%4];"
                 : "=r"(r0), "=r"(r1), "=r"(r2), "=r"(r3) : "r"(a));
}

__device__ __forceinline__ void mma16816(float d[4], unsigned a0, unsigned a1, unsigned a2,
                                         unsigned a3, unsigned b0, unsigned b1) {
    asm volatile("mma.sync.aligned.m16n8k16.row.col.f32.bf16.bf16.f32 "
                 "{%0,%1,%2,%3},{%4,%5,%6,%7},{%8,%9},{%0,%1,%2,%3};"
                 : "+f"(d[0]), "+f"(d[1]), "+f"(d[2]), "+f"(d[3])
                 : "r"(a0), "r"(a1), "r"(a2), "r"(a3), "r"(b0), "r"(b1));
}

// MUFU.TANH — single-instruction nonlinearities
__device__ __forceinline__ float tanhap(float x) {
    float y;
    asm("tanh.approx.f32 %0, %1;" : "=f"(y) : "f"(x));
    return y;
}
__device__ __forceinline__ float sigm(float v) {
    return fmaf(tanhap(0.5f * v), 0.5f, 0.5f);
}

// Dual-stream GEMM, pure bf16: acc += a_bf16 @ W_bf16 (fp32 accumulate).
// W fragments loaded ONCE per ks, shared by both streams. m16n16 per stream.
__device__ __forceinline__ void gemm_dual(float accA[2][4], float accB[2][4], unsigned sb,
                                          unsigned aH, unsigned wB,
                                          unsigned raA, unsigned raB, unsigned cbOff) {
    #pragma unroll
    for (int ks = 0; ks < 4; ++ks) {
        unsigned bh0, bh1, bh2, bh3;
        ldsm4(bh0, bh1, bh2, bh3, sb + wB + swz(cbOff + ks * 32));
        unsigned a0, a1, a2, a3;
        ldsm4(a0, a1, a2, a3, sb + aH + swz(raA + ks * 32));
        mma16816(accA[0], a0, a1, a2, a3, bh0, bh1);
        mma16816(accA[1], a0, a1, a2, a3, bh2, bh3);
        unsigned c0, c1, c2, c3;
        ldsm4(c0, c1, c2, c3, sb + aH + swz(raB + ks * 32));
        mma16816(accB[0], c0, c1, c2, c3, bh0, bh1);
        mma16816(accB[1], c0, c1, c2, c3, bh2, bh3);
    }
}

// Shuffle-free cell: lane owns ALL 4 gates of one unit for rows rA, rB.
// acc[0] = (i,f) x (rA,rB); acc[1] = (g,o) x (rA,rB).
__device__ __forceinline__ void cell_ns(const float acc[2][4], float cst[2], float hvo[2]) {
    {
        float cn = sigm(acc[0][1]) * cst[0] + sigm(acc[0][0]) * tanhap(acc[1][0]);
        cst[0] = cn;
        hvo[0] = sigm(acc[1][1]) * tanhap(cn);
    }
    {
        float cn = sigm(acc[0][3]) * cst[1] + sigm(acc[0][2]) * tanhap(acc[1][2]);
        cst[1] = cn;
        hvo[1] = sigm(acc[1][3]) * tanhap(cn);
    }
}

// Store owned unit's h (bf16) for rows rA, rB.
__device__ __forceinline__ void store_s(char *smp, unsigned offH,
                                        const float hvo[2], int uo, int rA, int rB) {
    unsigned oA = swz((unsigned)(rA * 128 + uo * 2));
    unsigned oB = swz((unsigned)(rB * 128 + uo * 2));
    *(__nv_bfloat16 *)(smp + offH + oA) = __float2bfloat16(hvo[0]);
    *(__nv_bfloat16 *)(smp + offH + oB) = __float2bfloat16(hvo[1]);
}

// Store raw fp32 weights [256 gate-rows][64 k] into gate-per-lane interleaved
// swizzled bf16. Raw row R = gate*64 + u. Column:
//   C = 16*(u>>2) + 8*(gate>>1) + 2*(u&3) + (gate&1)
// so warp jw's 16 cols hold units 4jw..4jw+3, each lane q owning its unit's
// (i,f) in tile0 and (g,o) in tile1.
__device__ void store_w(char *smp, unsigned off, const float *__restrict__ raw) {
    for (int e = threadIdx.x; e < 256 * 64; e += NTH) {
        int R = e >> 6, k = e & 63;
        int gate = R >> 6, u = R & 63;
        int C = 16 * (u >> 2) + 8 * (gate >> 1) + 2 * (u & 3) + (gate & 1);
        unsigned o = swz((unsigned)(C * 128 + k * 2));
        *(__nv_bfloat16 *)(smp + off + o) = __float2bfloat16(raw[e]);
    }
}

__global__ void __launch_bounds__(NTH, 1)
lstm_kernel(const float *__restrict__ x,
            const float *__restrict__ eWih0, const float *__restrict__ eWhh0,
            const float *__restrict__ eb0,
            const float *__restrict__ eWih1, const float *__restrict__ eWhh1,
            const float *__restrict__ eb1,
            const float *__restrict__ dWih0, const float *__restrict__ dWhh0,
            const float *__restrict__ db0,
            const float *__restrict__ dWih1, const float *__restrict__ dWhh1,
            const float *__restrict__ db1,
            const float *__restrict__ fcW, const float *__restrict__ fcb,
            float *__restrict__ out) {
    extern __shared__ char smem[];
    unsigned sb = (unsigned)__cvta_generic_to_shared(smem);

    const int tid = threadIdx.x;
    const int lane = tid & 31;
    const int jw = tid >> 5;           // warp = n16 block: units 4jw..4jw+3
    const int blk = blockIdx.x;

    const int rA = lane >> 2;          // stream-local rows rA, rA+8
    const int rB = rA + 8;
    const int uo = 4 * jw + (lane & 3);  // this lane's unit (all 4 gates)

    const unsigned raA = (unsigned)(((lane & 7) + (lane & 8)) * 128 + ((lane >> 4) & 1) * 16);
    const unsigned raB = raA + 16 * 128;
    const unsigned cbOff = (unsigned)((16 * jw + (lane & 7) + 8 * ((lane >> 4) & 1)) * 128
                                      + ((lane >> 3) & 1) * 16);

    // lane's gate-rows in raw order: cI[nt][p] = gate (2nt+p) of unit uo
    int cI[2][2];
    #pragma unroll
    for (int nt = 0; nt < 2; ++nt) {
        cI[nt][0] = (2 * nt + 0) * 64 + uo;
        cI[nt][1] = (2 * nt + 1) * 64 + uo;
    }

    // ---------- encoder weights ----------
    store_w(smem, OFF_W0, eWhh0);
    store_w(smem, OFF_W1A, eWih1);
    store_w(smem, OFF_W1B, eWhh1);
    for (int i = tid; i < 4096; i += NTH) ((float *)(smem + OFF_AH0))[i] = 0.f;  // 16KB h bufs

    float b0c[2][2], b1c[2][2], wic[2][2];
    #pragma unroll
    for (int nt = 0; nt < 2; ++nt) {
        b0c[nt][0] = eb0[cI[nt][0]]; b0c[nt][1] = eb0[cI[nt][1]];
        b1c[nt][0] = eb1[cI[nt][0]]; b1c[nt][1] = eb1[cI[nt][1]];
        wic[nt][0] = eWih0[cI[nt][0]]; wic[nt][1] = eWih0[cI[nt][1]];
    }
    __syncthreads();

    float c0A[2] = {0.f, 0.f}, c0B[2] = {0.f, 0.f};
    float c1A[2] = {0.f, 0.f}, c1B[2] = {0.f, 0.f};

    const float *xbase = x + blk * 32 * TT;
    float xv[4];
    xv[0] = xbase[rA * TT];
    xv[1] = xbase[rB * TT];
    xv[2] = xbase[(rA + 16) * TT];
    xv[3] = xbase[(rB + 16) * TT];

    // ---------- encoder: 365 steps, 1 barrier/step, dual-stream ILP ----------
    for (int t = 0; t < TT; ++t) {
        float xn[4] = {0.f, 0.f, 0.f, 0.f};
        if (t + 1 < TT) {
            xn[0] = xbase[rA * TT + t + 1];
            xn[1] = xbase[rB * TT + t + 1];
            xn[2] = xbase[(rA + 16) * TT + t + 1];
            xn[3] = xbase[(rB + 16) * TT + t + 1];
        }
        unsigned h0r = OFF_AH0 + (unsigned)(t & 1) * 4096u;
        unsigned h0w = OFF_AH0 + (unsigned)((t + 1) & 1) * 4096u;
        unsigned h1r = OFF_AH1 + (unsigned)(t & 1) * 4096u;
        unsigned h1w = OFF_AH1 + (unsigned)((t + 1) & 1) * 4096u;

        // phase 1: layer 0 for both streams
        float aA[2][4], aB[2][4];
        #pragma unroll
        for (int nt = 0; nt < 2; ++nt) {
            aA[nt][0] = fmaf(xv[0], wic[nt][0], b0c[nt][0]);
            aA[nt][1] = fmaf(xv[0], wic[nt][1], b0c[nt][1]);
            aA[nt][2] = fmaf(xv[1], wic[nt][0], b0c[nt][0]);
            aA[nt][3] = fmaf(xv[1], wic[nt][1], b0c[nt][1]);
            aB[nt][0] = fmaf(xv[2], wic[nt][0], b0c[nt][0]);
            aB[nt][1] = fmaf(xv[2], wic[nt][1], b0c[nt][1]);
            aB[nt][2] = fmaf(xv[3], wic[nt][0], b0c[nt][0]);
            aB[nt][3] = fmaf(xv[3], wic[nt][1], b0c[nt][1]);
        }
        gemm_dual(aA, aB, sb, h0r, OFF_W0, raA, raB, cbOff);
        float hA[2], hB[2];
        cell_ns(aA, c0A, hA);
        cell_ns(aB, c0B, hB);
        store_s(smem, h0w, hA, uo, rA, rB);
        store_s(smem, h0w, hB, uo, rA + 16, rB + 16);
        __syncthreads();

        // phase 2: layer 1 for both streams (K=128: h0_cur + h1_prev)
        #pragma unroll
        for (int nt = 0; nt < 2; ++nt) {
            aA[nt][0] = b1c[nt][0]; aA[nt][1] = b1c[nt][1];
            aA[nt][2] = b1c[nt][0]; aA[nt][3] = b1c[nt][1];
            aB[nt][0] = b1c[nt][0]; aB[nt][1] = b1c[nt][1];
            aB[nt][2] = b1c[nt][0]; aB[nt][3] = b1c[nt][1];
        }
        gemm_dual(aA, aB, sb, h0w, OFF_W1A, raA, raB, cbOff);
        gemm_dual(aA, aB, sb, h1r, OFF_W1B, raA, raB, cbOff);
        cell_ns(aA, c1A, hA);
        cell_ns(aB, c1B, hB);
        store_s(smem, h1w, hA, uo, rA, rB);
        store_s(smem, h1w, hB, uo, rA + 16, rB + 16);
        // no 2nd barrier: next step's barrier covers h1 visibility + WAR

        xv[0] = xn[0]; xv[1] = xn[1]; xv[2] = xn[2]; xv[3] = xn[3];
    }
    __syncthreads();

    // ---------- decoder weights ----------
    store_w(smem, OFF_W0, dWhh0);
    store_w(smem, OFF_W1A, dWih1);
    store_w(smem, OFF_W1B, dWhh1);
    #pragma unroll
    for (int nt = 0; nt < 2; ++nt) {
        b0c[nt][0] = db0[cI[nt][0]]; b0c[nt][1] = db0[cI[nt][1]];
        b1c[nt][0] = db1[cI[nt][0]]; b1c[nt][1] = db1[cI[nt][1]];
        wic[nt][0] = dWih0[cI[nt][0]]; wic[nt][1] = dWih0[cI[nt][1]];
    }
    const float fcw = fcW[uo];
    const float fcbv = fcb[0];
    __syncthreads();

    // ---------- decoder: 7 autoregressive steps ----------
    float din[4] = {0.f, 0.f, 0.f, 0.f};
    for (int s = 0; s < HORIZON; ++s) {
        unsigned rp = (unsigned)((TT + s) & 1);
        unsigned h0r = OFF_AH0 + rp * 4096u, h0w = OFF_AH0 + (rp ^ 1) * 4096u;
        unsigned h1r = OFF_AH1 + rp * 4096u, h1w = OFF_AH1 + (rp ^ 1) * 4096u;

        float aA[2][4], aB[2][4];
        #pragma unroll
        for (int nt = 0; nt < 2; ++nt) {
            aA[nt][0] = fmaf(din[0], wic[nt][0], b0c[nt][0]);
            aA[nt][1] = fmaf(din[0], wic[nt][1], b0c[nt][1]);
            aA[nt][2] = fmaf(din[1], wic[nt][0], b0c[nt][0]);
            aA[nt][3] = fmaf(din[1], wic[nt][1], b0c[nt][1]);
            aB[nt][0] = fmaf(din[2], wic[nt][0], b0c[nt][0]);
            aB[nt][1] = fmaf(din[2], wic[nt][1], b0c[nt][1]);
            aB[nt][2] = fmaf(din[3], wic[nt][0], b0c[nt][0]);
            aB[nt][3] = fmaf(din[3], wic[nt][1], b0c[nt][1]);
        }
        gemm_dual(aA, aB, sb, h0r, OFF_W0, raA, raB, cbOff);
        float hA[2], hB[2];
        cell_ns(aA, c0A, hA);
        cell_ns(aB, c0B, hB);
        store_s(smem, h0w, hA, uo, rA, rB);
        store_s(smem, h0w, hB, uo, rA + 16, rB + 16);
        __syncthreads();

        #pragma unroll
        for (int nt = 0; nt < 2; ++nt) {
            aA[nt][0] = b1c[nt][0]; aA[nt][1] = b1c[nt][1];
            aA[nt][2] = b1c[nt][0]; aA[nt][3] = b1c[nt][1];
            aB[nt][0] = b1c[nt][0]; aB[nt][1] = b1c[nt][1];
            aB[nt][2] = b1c[nt][0]; aB[nt][3] = b1c[nt][1];
        }
        gemm_dual(aA, aB, sb, h0w, OFF_W1A, raA, raB, cbOff);
        gemm_dual(aA, aB, sb, h1r, OFF_W1B, raA, raB, cbOff);
        cell_ns(aA, c1A, hA);
        cell_ns(aB, c1B, hB);
        store_s(smem, h1w, hA, uo, rA, rB);
        store_s(smem, h1w, hB, uo, rA + 16, rB + 16);

        // FC: lane contributes its unit; quad shfl sums 4 units/warp
        float vA0 = hA[0] * fcw, vA1 = hA[1] * fcw;
        float vB0 = hB[0] * fcw, vB1 = hB[1] * fcw;
        vA0 += __shfl_xor_sync(0xFFFFFFFFu, vA0, 1);
        vA1 += __shfl_xor_sync(0xFFFFFFFFu, vA1, 1);
        vB0 += __shfl_xor_sync(0xFFFFFFFFu, vB0, 1);
        vB1 += __shfl_xor_sync(0xFFFFFFFFu, vB1, 1);
        vA0 += __shfl_xor_sync(0xFFFFFFFFu, vA0, 2);
        vA1 += __shfl_xor_sync(0xFFFFFFFFu, vA1, 2);
        vB0 += __shfl_xor_sync(0xFFFFFFFFu, vB0, 2);
        vB1 += __shfl_xor_sync(0xFFFFFFFFu, vB1, 2);
        if ((lane & 3) == 0) {
            g_pp[blk][jw][rA] = vA0;
            g_pp[blk][jw][rB] = vA1;
            g_pp[blk][jw][rA + 16] = vB0;
            g_pp[blk][jw][rB + 16] = vB1;
        }
        __syncthreads();
        if (tid < 32) {
            float sum = fcbv;
            #pragma unroll
            for (int j = 0; j < 16; ++j) sum += g_pp[blk][j][tid];
            out[(blk * 32 + tid) * HORIZON + s] = sum;
            g_fb[blk][tid] = sum;
        }
        __syncthreads();
        din[0] = g_fb[blk][rA];
        din[1] = g_fb[blk][rB];
        din[2] = g_fb[blk][rA + 16];
        din[3] = g_fb[blk][rB + 16];
    }
}

extern "C" void kernel_launch(void *const *d_in, const int *in_sizes, int n_in,
                              void *d_out, int out_size) {
    cudaFuncSetAttribute(lstm_kernel, cudaFuncAttributeMaxDynamicSharedMemorySize, SMEM_BYTES);
    lstm_kernel<<<NCTA, NTH, SMEM_BYTES>>>(
        (const float *)d_in[0],
        (const float *)d_in[1], (const float *)d_in[2], (const float *)d_in[3],
        (const float *)d_in[4], (const float *)d_in[5], (const float *)d_in[6],
        (const float *)d_in[7], (const float *)d_in[8], (const float *)d_in[9],
        (const float *)d_in[10], (const float *)d_in[11], (const float *)d_in[12],
        (const float *)d_in[13], (const float *)d_in[14],
        (float *)d_out);
}